// round 1
// baseline (speedup 1.0000x reference)
#include <cuda_runtime.h>

#define B_  8
#define C_  512
#define S_  1024
#define NH_ 8
#define HD_ 64

// Scratch (static device globals — no allocation allowed)
__device__ float g_h [B_*C_*S_];   // groupnorm output [b][c][s]
__device__ float g_q [B_*C_*S_];   // q [b][c][s]  (c = n*64+d)
__device__ float g_k [B_*C_*S_];
__device__ float g_v [B_*C_*S_];
__device__ float g_f0[B_*S_*C_];   // h_flat ping [b][s][c]
__device__ float g_f1[B_*S_*C_];   // h_flat pong

// ---------------------------------------------------------------------------
// GroupNorm: 1 block per (b, group). group = 64 channels x 1024 spatial.
// ---------------------------------------------------------------------------
__global__ void gn_kernel(const float* __restrict__ x,
                          const float* __restrict__ sc,
                          const float* __restrict__ bi) {
    int b = blockIdx.x >> 3, g = blockIdx.x & 7;
    int base = (b * C_ + g * 64) * S_;
    const float4* xp = (const float4*)(x + base);
    float4* op = (float4*)(g_h + base);
    const int N4 = 64 * S_ / 4;   // 16384 float4s
    float s = 0.f, ss = 0.f;
    for (int i = threadIdx.x; i < N4; i += 256) {
        float4 v = xp[i];
        s  += v.x + v.y + v.z + v.w;
        ss += v.x*v.x + v.y*v.y + v.z*v.z + v.w*v.w;
    }
    #pragma unroll
    for (int o = 16; o; o >>= 1) {
        s  += __shfl_xor_sync(0xffffffffu, s,  o);
        ss += __shfl_xor_sync(0xffffffffu, ss, o);
    }
    __shared__ float red[16];
    int wid = threadIdx.x >> 5;
    if ((threadIdx.x & 31) == 0) { red[wid] = s; red[8 + wid] = ss; }
    __syncthreads();
    if (threadIdx.x == 0) {
        float S = 0.f, SS = 0.f;
        #pragma unroll
        for (int w = 0; w < 8; w++) { S += red[w]; SS += red[8 + w]; }
        float mean = S * (1.f / 65536.f);
        float var  = SS * (1.f / 65536.f) - mean * mean;
        red[0] = mean;
        red[1] = rsqrtf(var + 1e-5f);
    }
    __syncthreads();
    float mean = red[0], inv = red[1];
    for (int i = threadIdx.x; i < N4; i += 256) {
        int c = g * 64 + (i >> 8);       // 256 float4 per channel
        float a = sc[c] * inv;
        float bb = bi[c] - mean * a;
        float4 v = xp[i];
        v.x = v.x*a + bb; v.y = v.y*a + bb; v.z = v.z*a + bb; v.w = v.w*a + bb;
        op[i] = v;
    }
}

// ---------------------------------------------------------------------------
// QKV: C[o,s] = sum_c W[o,c] * h[b][c][s] + bias[o].  64x64 tile, BK=16.
// Output routed to g_q / g_k / g_v in [b][c][s] layout.
// ---------------------------------------------------------------------------
__global__ void qkv_kernel(const float* __restrict__ W,
                           const float* __restrict__ bias) {
    __shared__ float As[16][68];   // W^T tile: As[c][o]
    __shared__ float Bs[16][64];   // h tile:   Bs[c][s]
    int b = blockIdx.z, o0 = blockIdx.y * 64, s0 = blockIdx.x * 64;
    int u = threadIdx.x, tx = u & 15, ty = u >> 4;
    const float* hb = g_h + b * C_ * S_;
    int arow = u >> 2, acol = (u & 3) * 4;
    int bk = u >> 4, bs4 = (u & 15) * 4;
    float acc[4][4] = {};
    for (int k0 = 0; k0 < C_; k0 += 16) {
        float4 a = *(const float4*)&W[(o0 + arow) * C_ + k0 + acol];
        As[acol+0][arow] = a.x; As[acol+1][arow] = a.y;
        As[acol+2][arow] = a.z; As[acol+3][arow] = a.w;
        *(float4*)&Bs[bk][bs4] = *(const float4*)&hb[(k0 + bk) * S_ + s0 + bs4];
        __syncthreads();
        #pragma unroll
        for (int k = 0; k < 16; k++) {
            float4 av = *(const float4*)&As[k][ty*4];
            float4 bv = *(const float4*)&Bs[k][tx*4];
            float a_[4] = {av.x, av.y, av.z, av.w};
            float b_[4] = {bv.x, bv.y, bv.z, bv.w};
            #pragma unroll
            for (int i = 0; i < 4; i++)
                #pragma unroll
                for (int j = 0; j < 4; j++) acc[i][j] += a_[i] * b_[j];
        }
        __syncthreads();
    }
    int sel = o0 >> 9;
    float* outp = (sel == 0) ? g_q : (sel == 1) ? g_k : g_v;
    outp += b * C_ * S_;
    int oo0 = o0 & 511;
    #pragma unroll
    for (int i = 0; i < 4; i++) {
        float bv = bias[o0 + ty*4 + i];
        *(float4*)&outp[(oo0 + ty*4 + i) * S_ + s0 + tx*4] =
            make_float4(acc[i][0]+bv, acc[i][1]+bv, acc[i][2]+bv, acc[i][3]+bv);
    }
}

// ---------------------------------------------------------------------------
// Flash attention: block = (b, head, 64-row q tile). smem exactly 48KB.
// K buffer is reused for P after the QK pass. V stored transposed with
// a 16B-granularity XOR swizzle (conflict-free PV reads).
// ---------------------------------------------------------------------------
__global__ void attn_kernel() {
    __shared__ float Qs [64][64];
    __shared__ float KPs[64][64];
    __shared__ float Vs [64][64];
    int bn = blockIdx.y;
    int base = ((bn >> 3) * C_ + (bn & 7) * HD_) * S_;
    int s0 = blockIdx.x * 64;
    const float* Qg = g_q + base;
    const float* Kg = g_k + base;
    const float* Vg = g_v + base;
    int u = threadIdx.x, tx = u & 15, ty = u >> 4;

    #pragma unroll
    for (int r = 0; r < 4; r++) {
        int idx = u + r * 256;
        int d = idx >> 4, c4 = (idx & 15) * 4;
        float4 q = *(const float4*)&Qg[d * S_ + s0 + c4];
        q.x *= 0.125f; q.y *= 0.125f; q.z *= 0.125f; q.w *= 0.125f;  // hd^-0.5
        *(float4*)&Qs[d][c4] = q;
    }
    float o_acc[4][4] = {};
    float m[4], l[4];
    #pragma unroll
    for (int i = 0; i < 4; i++) { m[i] = -1e30f; l[i] = 0.f; }

    for (int t0 = 0; t0 < S_; t0 += 64) {
        __syncthreads();  // Q ready / previous PV reads done
        #pragma unroll
        for (int r = 0; r < 4; r++) {
            int idx = u + r * 256;
            int d = idx >> 4, t4 = (idx & 15) * 4;
            *(float4*)&KPs[d][t4] = *(const float4*)&Kg[d * S_ + t0 + t4];
            float4 v = *(const float4*)&Vg[d * S_ + t0 + t4];
            int cg = d >> 2, dl = d & 3;
            Vs[t4+0][((cg ^ ((t4+0) & 15)) << 2) + dl] = v.x;
            Vs[t4+1][((cg ^ ((t4+1) & 15)) << 2) + dl] = v.y;
            Vs[t4+2][((cg ^ ((t4+2) & 15)) << 2) + dl] = v.z;
            Vs[t4+3][((cg ^ ((t4+3) & 15)) << 2) + dl] = v.w;
        }
        __syncthreads();

        float sacc[4][4] = {};
        #pragma unroll
        for (int k = 0; k < 64; k++) {
            float4 av = *(const float4*)&Qs[k][ty*4];
            float4 bv = *(const float4*)&KPs[k][tx*4];
            float a_[4] = {av.x, av.y, av.z, av.w};
            float b_[4] = {bv.x, bv.y, bv.z, bv.w};
            #pragma unroll
            for (int i = 0; i < 4; i++)
                #pragma unroll
                for (int j = 0; j < 4; j++) sacc[i][j] += a_[i] * b_[j];
        }
        // online softmax update (row stats live across tx lanes, bits 0..3)
        float mloc[4], lloc[4];
        #pragma unroll
        for (int i = 0; i < 4; i++)
            mloc[i] = fmaxf(fmaxf(sacc[i][0], sacc[i][1]),
                            fmaxf(sacc[i][2], sacc[i][3]));
        #pragma unroll
        for (int off = 1; off < 16; off <<= 1)
            #pragma unroll
            for (int i = 0; i < 4; i++)
                mloc[i] = fmaxf(mloc[i], __shfl_xor_sync(0xffffffffu, mloc[i], off));
        #pragma unroll
        for (int i = 0; i < 4; i++) {
            float mn = fmaxf(m[i], mloc[i]);
            float fac = __expf(m[i] - mn);
            m[i] = mn;
            l[i] *= fac;
            #pragma unroll
            for (int j = 0; j < 4; j++) o_acc[i][j] *= fac;
            lloc[i] = 0.f;
            #pragma unroll
            for (int j = 0; j < 4; j++) {
                sacc[i][j] = __expf(sacc[i][j] - mn);
                lloc[i] += sacc[i][j];
            }
        }
        #pragma unroll
        for (int off = 1; off < 16; off <<= 1)
            #pragma unroll
            for (int i = 0; i < 4; i++)
                lloc[i] += __shfl_xor_sync(0xffffffffu, lloc[i], off);
        #pragma unroll
        for (int i = 0; i < 4; i++) l[i] += lloc[i];

        __syncthreads();  // done reading K from KPs
        #pragma unroll
        for (int i = 0; i < 4; i++)
            *(float4*)&KPs[ty*4+i][tx*4] =
                make_float4(sacc[i][0], sacc[i][1], sacc[i][2], sacc[i][3]);
        __syncthreads();

        #pragma unroll
        for (int k = 0; k < 64; k++) {
            float a0 = KPs[ty*4+0][k];   // broadcast reads
            float a1 = KPs[ty*4+1][k];
            float a2 = KPs[ty*4+2][k];
            float a3 = KPs[ty*4+3][k];
            float4 bv = *(const float4*)&Vs[k][(tx ^ (k & 15)) << 2];
            float b_[4] = {bv.x, bv.y, bv.z, bv.w};
            #pragma unroll
            for (int j = 0; j < 4; j++) {
                o_acc[0][j] += a0 * b_[j];
                o_acc[1][j] += a1 * b_[j];
                o_acc[2][j] += a2 * b_[j];
                o_acc[3][j] += a3 * b_[j];
            }
        }
    }
    int b = bn >> 3, n = bn & 7;
    float* outp = g_f0 + (b * S_ + s0) * C_ + n * HD_;
    #pragma unroll
    for (int i = 0; i < 4; i++) {
        float inv = 1.f / l[i];
        *(float4*)&outp[(ty*4+i) * C_ + tx*4] =
            make_float4(o_acc[i][0]*inv, o_acc[i][1]*inv,
                        o_acc[i][2]*inv, o_acc[i][3]*inv);
    }
}

// ---------------------------------------------------------------------------
// INL step: hout[m][o] = hin[m][o] + 0.1*tanh( sum_c hin[m][c]*W[o][c] + b[o] )
// NT GEMM, M = B*S = 8192, N = K = 512.  flip selects ping/pong direction.
// ---------------------------------------------------------------------------
__global__ void inl_kernel(int flip, const float* __restrict__ W,
                           const float* __restrict__ bias) {
    const float* hin  = flip ? g_f1 : g_f0;
    float*       hout = flip ? g_f0 : g_f1;
    __shared__ float As[16][68];   // hin^T tile
    __shared__ float Bs[16][68];   // W^T tile
    int m0 = blockIdx.y * 64, o0 = blockIdx.x * 64;
    int u = threadIdx.x, tx = u & 15, ty = u >> 4;
    int row = u >> 2, c4 = (u & 3) * 4;
    float acc[4][4] = {};
    for (int k0 = 0; k0 < C_; k0 += 16) {
        float4 a = *(const float4*)&hin[(m0 + row) * C_ + k0 + c4];
        As[c4+0][row]=a.x; As[c4+1][row]=a.y; As[c4+2][row]=a.z; As[c4+3][row]=a.w;
        float4 w = *(const float4*)&W[(o0 + row) * C_ + k0 + c4];
        Bs[c4+0][row]=w.x; Bs[c4+1][row]=w.y; Bs[c4+2][row]=w.z; Bs[c4+3][row]=w.w;
        __syncthreads();
        #pragma unroll
        for (int k = 0; k < 16; k++) {
            float4 av = *(const float4*)&As[k][ty*4];
            float4 bv = *(const float4*)&Bs[k][tx*4];
            float a_[4] = {av.x, av.y, av.z, av.w};
            float b_[4] = {bv.x, bv.y, bv.z, bv.w};
            #pragma unroll
            for (int i = 0; i < 4; i++)
                #pragma unroll
                for (int j = 0; j < 4; j++) acc[i][j] += a_[i] * b_[j];
        }
        __syncthreads();
    }
    float bv[4];
    #pragma unroll
    for (int j = 0; j < 4; j++) bv[j] = bias[o0 + tx*4 + j];
    #pragma unroll
    for (int i = 0; i < 4; i++) {
        int mm = m0 + ty*4 + i;
        float4 h = *(const float4*)&hin[mm * C_ + o0 + tx*4];
        h.x += 0.1f * tanhf(acc[i][0] + bv[0]);
        h.y += 0.1f * tanhf(acc[i][1] + bv[1]);
        h.z += 0.1f * tanhf(acc[i][2] + bv[2]);
        h.w += 0.1f * tanhf(acc[i][3] + bv[3]);
        *(float4*)&hout[mm * C_ + o0 + tx*4] = h;
    }
}

// ---------------------------------------------------------------------------
// Projection + residual: out[b][o][s] = x[b][o][s] + b[o] + sum_c W[o][c]*h[b][s][c]
// Reads the final INL buffer g_f1.
// ---------------------------------------------------------------------------
__global__ void proj_kernel(const float* __restrict__ W,
                            const float* __restrict__ bias,
                            const float* __restrict__ x,
                            float* __restrict__ out) {
    __shared__ float As[16][68];   // W^T: As[c][o]
    __shared__ float Bs[16][68];   // h^T: Bs[c][s]
    int b = blockIdx.z, o0 = blockIdx.y * 64, s0 = blockIdx.x * 64;
    const float* hb = g_f1 + b * S_ * C_;
    int u = threadIdx.x, tx = u & 15, ty = u >> 4;
    int row = u >> 2, c4 = (u & 3) * 4;
    float acc[4][4] = {};
    for (int k0 = 0; k0 < C_; k0 += 16) {
        float4 a = *(const float4*)&W[(o0 + row) * C_ + k0 + c4];
        As[c4+0][row]=a.x; As[c4+1][row]=a.y; As[c4+2][row]=a.z; As[c4+3][row]=a.w;
        float4 h = *(const float4*)&hb[(s0 + row) * C_ + k0 + c4];
        Bs[c4+0][row]=h.x; Bs[c4+1][row]=h.y; Bs[c4+2][row]=h.z; Bs[c4+3][row]=h.w;
        __syncthreads();
        #pragma unroll
        for (int k = 0; k < 16; k++) {
            float4 av = *(const float4*)&As[k][ty*4];
            float4 bv = *(const float4*)&Bs[k][tx*4];
            float a_[4] = {av.x, av.y, av.z, av.w};
            float b_[4] = {bv.x, bv.y, bv.z, bv.w};
            #pragma unroll
            for (int i = 0; i < 4; i++)
                #pragma unroll
                for (int j = 0; j < 4; j++) acc[i][j] += a_[i] * b_[j];
        }
        __syncthreads();
    }
    #pragma unroll
    for (int i = 0; i < 4; i++) {
        int o = o0 + ty*4 + i;
        float pb = bias[o];
        int addr = (b * C_ + o) * S_ + s0 + tx*4;
        float4 xv = *(const float4*)&x[addr];
        *(float4*)&out[addr] =
            make_float4(acc[i][0]+pb+xv.x, acc[i][1]+pb+xv.y,
                        acc[i][2]+pb+xv.z, acc[i][3]+pb+xv.w);
    }
}

// ---------------------------------------------------------------------------
extern "C" void kernel_launch(void* const* d_in, const int* in_sizes, int n_in,
                              void* d_out, int out_size) {
    const float* x        = (const float*)d_in[0];
    const float* gn_scale = (const float*)d_in[1];
    const float* gn_bias  = (const float*)d_in[2];
    const float* qkv_w    = (const float*)d_in[3];
    const float* qkv_b    = (const float*)d_in[4];
    const float* proj_w   = (const float*)d_in[5];
    const float* proj_b   = (const float*)d_in[6];
    const float* inl_w    = (const float*)d_in[7];
    const float* inl_b    = (const float*)d_in[8];
    float* out = (float*)d_out;

    gn_kernel  <<<64, 256>>>(x, gn_scale, gn_bias);
    qkv_kernel <<<dim3(16, 24, 8), 256>>>(qkv_w, qkv_b);
    attn_kernel<<<dim3(16, 64),    256>>>();
    inl_kernel <<<dim3(8, 128),    256>>>(0, inl_w, inl_b);  // f0 -> f1
    inl_kernel <<<dim3(8, 128),    256>>>(1, inl_w, inl_b);  // f1 -> f0
    inl_kernel <<<dim3(8, 128),    256>>>(0, inl_w, inl_b);  // f0 -> f1
    proj_kernel<<<dim3(16, 8, 8),  256>>>(proj_w, proj_b, x, out);
}

// round 3
// speedup vs baseline: 1.2039x; 1.2039x over previous
#include <cuda_runtime.h>

#define B_  8
#define C_  512
#define S_  1024
#define NH_ 8
#define HD_ 64

// Scratch (static device globals — no allocation allowed)
__device__ float g_h [B_*C_*S_];   // groupnorm output [b][c][s]
__device__ float g_q [B_*C_*S_];   // q [b][c][s]  (c = n*64+d)
__device__ float g_k [B_*C_*S_];
__device__ float g_v [B_*C_*S_];
__device__ float g_f0[B_*S_*C_];   // h_flat ping [b][s][c]
__device__ float g_f1[B_*S_*C_];   // h_flat pong

// ---------------------------------------------------------------------------
// GroupNorm: 1 block (1024 thr) per (b, group). group = 64 ch x 1024 spatial.
// ---------------------------------------------------------------------------
__global__ void gn_kernel(const float* __restrict__ x,
                          const float* __restrict__ sc,
                          const float* __restrict__ bi) {
    int b = blockIdx.x >> 3, g = blockIdx.x & 7;
    int base = (b * C_ + g * 64) * S_;
    const float4* xp = (const float4*)(x + base);
    float4* op = (float4*)(g_h + base);
    const int N4 = 64 * S_ / 4;   // 16384 float4s
    float s = 0.f, ss = 0.f;
    for (int i = threadIdx.x; i < N4; i += 1024) {
        float4 v = xp[i];
        s  += v.x + v.y + v.z + v.w;
        ss += v.x*v.x + v.y*v.y + v.z*v.z + v.w*v.w;
    }
    #pragma unroll
    for (int o = 16; o; o >>= 1) {
        s  += __shfl_xor_sync(0xffffffffu, s,  o);
        ss += __shfl_xor_sync(0xffffffffu, ss, o);
    }
    __shared__ float red[64];
    int wid = threadIdx.x >> 5;
    if ((threadIdx.x & 31) == 0) { red[wid] = s; red[32 + wid] = ss; }
    __syncthreads();
    if (threadIdx.x == 0) {
        float S = 0.f, SS = 0.f;
        #pragma unroll
        for (int w = 0; w < 32; w++) { S += red[w]; SS += red[32 + w]; }
        float mean = S * (1.f / 65536.f);
        float var  = SS * (1.f / 65536.f) - mean * mean;
        red[0] = mean;
        red[1] = rsqrtf(var + 1e-5f);
    }
    __syncthreads();
    float mean = red[0], inv = red[1];
    for (int i = threadIdx.x; i < N4; i += 1024) {
        int c = g * 64 + (i >> 8);       // 256 float4 per channel
        float a = sc[c] * inv;
        float bb = bi[c] - mean * a;
        float4 v = xp[i];
        v.x = v.x*a + bb; v.y = v.y*a + bb; v.z = v.z*a + bb; v.w = v.w*a + bb;
        op[i] = v;
    }
}

// ===========================================================================
// 128x128x8 double-buffered SGEMM cores, 256 threads, 8x8 microtile.
//   As[k][m] (transposed in smem), Bs[k][n].
// ===========================================================================

#define FMA_8x8(buf)                                                          \
    _Pragma("unroll")                                                         \
    for (int k = 0; k < 8; k++) {                                             \
        float4 a0 = *(const float4*)&As[buf][k][ty*4];                        \
        float4 a1 = *(const float4*)&As[buf][k][64 + ty*4];                   \
        float4 b0 = *(const float4*)&Bs[buf][k][tx*4];                        \
        float4 b1 = *(const float4*)&Bs[buf][k][64 + tx*4];                   \
        float av[8] = {a0.x,a0.y,a0.z,a0.w,a1.x,a1.y,a1.z,a1.w};              \
        float bv[8] = {b0.x,b0.y,b0.z,b0.w,b1.x,b1.y,b1.z,b1.w};              \
        _Pragma("unroll")                                                     \
        for (int i = 0; i < 8; i++)                                           \
            _Pragma("unroll")                                                 \
            for (int j = 0; j < 8; j++) acc[i][j] += av[i] * bv[j];           \
    }

#define SCATTER_A(buf, v)                                                     \
    As[buf][lk+0][lr] = v.x; As[buf][lk+1][lr] = v.y;                         \
    As[buf][lk+2][lr] = v.z; As[buf][lk+3][lr] = v.w;
#define SCATTER_B(buf, v)                                                     \
    Bs[buf][lk+0][lr] = v.x; Bs[buf][lk+1][lr] = v.y;                         \
    Bs[buf][lk+2][lr] = v.z; Bs[buf][lk+3][lr] = v.w;

// ---------------------------------------------------------------------------
// QKV: C[o][s] = sum_c W[o][c] h[b][c][s] + bias.  A=W transposed-load,
// B=h direct (k-major). Output routed to g_q/g_k/g_v in [c][s] layout.
// ---------------------------------------------------------------------------
__global__ __launch_bounds__(256, 2)
void qkv_kernel(const float* __restrict__ W, const float* __restrict__ bias) {
    __shared__ float As[2][8][128];
    __shared__ float Bs[2][8][128];
    int b = blockIdx.z, m0 = blockIdx.y * 128, n0 = blockIdx.x * 128;
    const float* hb = g_h + b * C_ * S_;
    int u = threadIdx.x, tx = u & 15, ty = u >> 4;
    int lr = u >> 1, lk = (u & 1) * 4;       // A transposed-load indices
    int br = u >> 5, bc = (u & 31) * 4;      // B direct-load indices
    float acc[8][8] = {};
    {
        float4 a = *(const float4*)&W[(m0 + lr) * C_ + lk];
        float4 bt = *(const float4*)&hb[br * S_ + n0 + bc];
        SCATTER_A(0, a);
        *(float4*)&Bs[0][br][bc] = bt;
    }
    __syncthreads();
    int buf = 0;
    for (int kt = 1; kt <= C_ / 8; kt++) {
        float4 a, bt;
        if (kt < C_ / 8) {
            a  = *(const float4*)&W[(m0 + lr) * C_ + kt*8 + lk];
            bt = *(const float4*)&hb[(kt*8 + br) * S_ + n0 + bc];
        }
        FMA_8x8(buf)
        if (kt < C_ / 8) {
            SCATTER_A(buf ^ 1, a);
            *(float4*)&Bs[buf ^ 1][br][bc] = bt;
        }
        __syncthreads();
        buf ^= 1;
    }
    #pragma unroll
    for (int i = 0; i < 8; i++) {
        int o = m0 + ((i & 4) ? 64 : 0) + ty * 4 + (i & 3);
        int sel = o >> 9;
        float* outp = ((sel == 0) ? g_q : (sel == 1) ? g_k : g_v)
                      + b * C_ * S_ + (o & 511) * S_;
        float bv = bias[o];
        #pragma unroll
        for (int jg = 0; jg < 2; jg++) {
            int n = n0 + jg * 64 + tx * 4;
            *(float4*)&outp[n] = make_float4(acc[i][jg*4+0] + bv,
                                             acc[i][jg*4+1] + bv,
                                             acc[i][jg*4+2] + bv,
                                             acc[i][jg*4+3] + bv);
        }
    }
}

// ---------------------------------------------------------------------------
// INL step: hout[m][o] = hin[m][o] + 0.1*tanh(sum_c hin[m][c]W[o][c] + b[o])
// A = hin (transposed-load), B = W (transposed-load). M=8192, N=K=512.
// ---------------------------------------------------------------------------
__global__ __launch_bounds__(256, 2)
void inl_kernel(int flip, const float* __restrict__ W,
                const float* __restrict__ bias) {
    const float* hin  = flip ? g_f1 : g_f0;
    float*       hout = flip ? g_f0 : g_f1;
    __shared__ float As[2][8][128];
    __shared__ float Bs[2][8][128];
    int m0 = blockIdx.y * 128, n0 = blockIdx.x * 128;
    int u = threadIdx.x, tx = u & 15, ty = u >> 4;
    int lr = u >> 1, lk = (u & 1) * 4;
    float acc[8][8] = {};
    {
        float4 a = *(const float4*)&hin[(m0 + lr) * C_ + lk];
        float4 w = *(const float4*)&W[(n0 + lr) * C_ + lk];
        SCATTER_A(0, a); SCATTER_B(0, w);
    }
    __syncthreads();
    int buf = 0;
    for (int kt = 1; kt <= C_ / 8; kt++) {
        float4 a, w;
        if (kt < C_ / 8) {
            a = *(const float4*)&hin[(m0 + lr) * C_ + kt*8 + lk];
            w = *(const float4*)&W[(n0 + lr) * C_ + kt*8 + lk];
        }
        FMA_8x8(buf)
        if (kt < C_ / 8) { SCATTER_A(buf ^ 1, a); SCATTER_B(buf ^ 1, w); }
        __syncthreads();
        buf ^= 1;
    }
    float bv[8];
    #pragma unroll
    for (int jg = 0; jg < 2; jg++) {
        float4 bq = *(const float4*)&bias[n0 + jg * 64 + tx * 4];
        bv[jg*4+0]=bq.x; bv[jg*4+1]=bq.y; bv[jg*4+2]=bq.z; bv[jg*4+3]=bq.w;
    }
    #pragma unroll
    for (int i = 0; i < 8; i++) {
        int mm = m0 + ((i & 4) ? 64 : 0) + ty * 4 + (i & 3);
        #pragma unroll
        for (int jg = 0; jg < 2; jg++) {
            int oo = n0 + jg * 64 + tx * 4;
            float4 h = *(const float4*)&hin[mm * C_ + oo];
            h.x += 0.1f * tanhf(acc[i][jg*4+0] + bv[jg*4+0]);
            h.y += 0.1f * tanhf(acc[i][jg*4+1] + bv[jg*4+1]);
            h.z += 0.1f * tanhf(acc[i][jg*4+2] + bv[jg*4+2]);
            h.w += 0.1f * tanhf(acc[i][jg*4+3] + bv[jg*4+3]);
            *(float4*)&hout[mm * C_ + oo] = h;
        }
    }
}

// ---------------------------------------------------------------------------
// Projection + residual: out[b][o][s] = x + b[o] + sum_c W[o][c]*hf[b][s][c]
// A = W (transposed-load), B = hf (transposed-load over s rows).
// ---------------------------------------------------------------------------
__global__ __launch_bounds__(256, 2)
void proj_kernel(const float* __restrict__ W, const float* __restrict__ bias,
                 const float* __restrict__ x, float* __restrict__ out) {
    __shared__ float As[2][8][128];
    __shared__ float Bs[2][8][128];
    int b = blockIdx.z, m0 = blockIdx.y * 128, n0 = blockIdx.x * 128;
    const float* hf = g_f1 + b * S_ * C_;
    int u = threadIdx.x, tx = u & 15, ty = u >> 4;
    int lr = u >> 1, lk = (u & 1) * 4;
    float acc[8][8] = {};
    {
        float4 a = *(const float4*)&W[(m0 + lr) * C_ + lk];
        float4 h = *(const float4*)&hf[(n0 + lr) * C_ + lk];
        SCATTER_A(0, a); SCATTER_B(0, h);
    }
    __syncthreads();
    int buf = 0;
    for (int kt = 1; kt <= C_ / 8; kt++) {
        float4 a, h;
        if (kt < C_ / 8) {
            a = *(const float4*)&W[(m0 + lr) * C_ + kt*8 + lk];
            h = *(const float4*)&hf[(n0 + lr) * C_ + kt*8 + lk];
        }
        FMA_8x8(buf)
        if (kt < C_ / 8) { SCATTER_A(buf ^ 1, a); SCATTER_B(buf ^ 1, h); }
        __syncthreads();
        buf ^= 1;
    }
    #pragma unroll
    for (int i = 0; i < 8; i++) {
        int o = m0 + ((i & 4) ? 64 : 0) + ty * 4 + (i & 3);
        float pb = bias[o];
        #pragma unroll
        for (int jg = 0; jg < 2; jg++) {
            int s = n0 + jg * 64 + tx * 4;
            int addr = (b * C_ + o) * S_ + s;
            float4 xv = *(const float4*)&x[addr];
            *(float4*)&out[addr] = make_float4(acc[i][jg*4+0] + pb + xv.x,
                                               acc[i][jg*4+1] + pb + xv.y,
                                               acc[i][jg*4+2] + pb + xv.z,
                                               acc[i][jg*4+3] + pb + xv.w);
        }
    }
}

// ---------------------------------------------------------------------------
// Flash attention: block = (b, head) x 128-row q tile, 256 threads.
// QK: 8q x 4t microtile; PV: 8q x 4d. P stored transposed in smem with an
// XOR-group swizzle so both its stores and PV fragment reads are float4.
// ---------------------------------------------------------------------------
__global__ __launch_bounds__(256, 2) void attn_kernel() {
    extern __shared__ float sm[];
    float* Qs = sm;                       // [64][128]   Qs[d][q]
    float* Ks = sm + 64*128;              // [64][64]    Ks[d][t]
    float* Vs = Ks + 64*64;               // [64][68]    Vs[t][d] (pad 68)
    float* Ps = Vs + 64*68;               // [64][128]   Ps[t][q] swizzled
    int bn = blockIdx.y;
    int base = ((bn >> 3) * C_ + (bn & 7) * HD_) * S_;
    int q0 = blockIdx.x * 128;
    const float* Qg = g_q + base;
    const float* Kg = g_k + base;
    const float* Vg = g_v + base;
    int u = threadIdx.x, tx = u & 15, ty = u >> 4;

    #pragma unroll
    for (int r = 0; r < 8; r++) {
        int i = u + r * 256;
        int d = i >> 5, q4 = (i & 31) * 4;
        float4 q = *(const float4*)&Qg[d * S_ + q0 + q4];
        q.x *= 0.125f; q.y *= 0.125f; q.z *= 0.125f; q.w *= 0.125f;
        *(float4*)&Qs[d * 128 + q4] = q;
    }
    float oa[8][4] = {};
    float m[8], l[8];
    #pragma unroll
    for (int i = 0; i < 8; i++) { m[i] = -1e30f; l[i] = 0.f; }

    for (int t0 = 0; t0 < S_; t0 += 64) {
        __syncthreads();   // prev PV reads of Vs/Ps done; Q visible (1st iter)
        #pragma unroll
        for (int r = 0; r < 4; r++) {
            int i = u + r * 256;
            int d = i >> 4, t4 = (i & 15) * 4;
            *(float4*)&Ks[d * 64 + t4] = *(const float4*)&Kg[d * S_ + t0 + t4];
            float4 v = *(const float4*)&Vg[d * S_ + t0 + t4];
            Vs[(t4+0)*68 + d] = v.x; Vs[(t4+1)*68 + d] = v.y;
            Vs[(t4+2)*68 + d] = v.z; Vs[(t4+3)*68 + d] = v.w;
        }
        __syncthreads();

        float s0[4][4] = {}, s1[4][4] = {};
        #pragma unroll 8
        for (int k = 0; k < 64; k++) {
            float4 a0 = *(const float4*)&Qs[k * 128 + ty * 4];
            float4 a1 = *(const float4*)&Qs[k * 128 + 64 + ty * 4];
            float4 bq = *(const float4*)&Ks[k * 64 + tx * 4];
            float av0[4] = {a0.x, a0.y, a0.z, a0.w};
            float av1[4] = {a1.x, a1.y, a1.z, a1.w};
            float bvv[4] = {bq.x, bq.y, bq.z, bq.w};
            #pragma unroll
            for (int i = 0; i < 4; i++)
                #pragma unroll
                for (int j = 0; j < 4; j++) {
                    s0[i][j] += av0[i] * bvv[j];
                    s1[i][j] += av1[i] * bvv[j];
                }
        }
        // online softmax
        float mloc[8], lloc[8];
        #pragma unroll
        for (int i = 0; i < 4; i++) {
            mloc[i]   = fmaxf(fmaxf(s0[i][0], s0[i][1]), fmaxf(s0[i][2], s0[i][3]));
            mloc[4+i] = fmaxf(fmaxf(s1[i][0], s1[i][1]), fmaxf(s1[i][2], s1[i][3]));
        }
        #pragma unroll
        for (int off = 1; off < 16; off <<= 1)
            #pragma unroll
            for (int i = 0; i < 8; i++)
                mloc[i] = fmaxf(mloc[i], __shfl_xor_sync(0xffffffffu, mloc[i], off));
        #pragma unroll
        for (int i = 0; i < 8; i++) {
            float mn = fmaxf(m[i], mloc[i]);
            float fac = __expf(m[i] - mn);
            m[i] = mn; l[i] *= fac;
            #pragma unroll
            for (int j = 0; j < 4; j++) oa[i][j] *= fac;
            float* srow = (i < 4) ? s0[i] : s1[i - 4];
            float acc = 0.f;
            #pragma unroll
            for (int j = 0; j < 4; j++) { srow[j] = __expf(srow[j] - mn); acc += srow[j]; }
            lloc[i] = acc;
        }
        #pragma unroll
        for (int off = 1; off < 16; off <<= 1)
            #pragma unroll
            for (int i = 0; i < 8; i++)
                lloc[i] += __shfl_xor_sync(0xffffffffu, lloc[i], off);
        #pragma unroll
        for (int i = 0; i < 8; i++) l[i] += lloc[i];

        // store P transposed (swizzled): row t = tx*4+j, col group = q>>2 ^ tx
        #pragma unroll
        for (int j = 0; j < 4; j++) {
            int t = tx * 4 + j;             // t>>2 == tx
            int g0 = (ty ^ tx) << 2;        // q group for rows ty*4..+3
            *(float4*)&Ps[t * 128 + g0]      = make_float4(s0[0][j], s0[1][j], s0[2][j], s0[3][j]);
            *(float4*)&Ps[t * 128 + 64 + g0] = make_float4(s1[0][j], s1[1][j], s1[2][j], s1[3][j]);
        }
        __syncthreads();

        #pragma unroll 8
        for (int k = 0; k < 64; k++) {
            int g = (ty ^ ((k >> 2) & 15)) << 2;
            float4 p0 = *(const float4*)&Ps[k * 128 + g];
            float4 p1 = *(const float4*)&Ps[k * 128 + 64 + g];
            float4 vv = *(const float4*)&Vs[k * 68 + tx * 4];
            float pv0[4] = {p0.x, p0.y, p0.z, p0.w};
            float pv1[4] = {p1.x, p1.y, p1.z, p1.w};
            float bvv[4] = {vv.x, vv.y, vv.z, vv.w};
            #pragma unroll
            for (int i = 0; i < 4; i++)
                #pragma unroll
                for (int j = 0; j < 4; j++) {
                    oa[i][j]   += pv0[i] * bvv[j];
                    oa[4+i][j] += pv1[i] * bvv[j];
                }
        }
    }
    int b = bn >> 3, n = bn & 7;
    float* outp = g_f0 + (b * S_ + q0) * C_ + n * HD_;
    #pragma unroll
    for (int i = 0; i < 8; i++) {
        int q = ((i & 4) ? 64 : 0) + ty * 4 + (i & 3);
        float inv = 1.f / l[i];
        *(float4*)&outp[q * C_ + tx * 4] =
            make_float4(oa[i][0]*inv, oa[i][1]*inv, oa[i][2]*inv, oa[i][3]*inv);
    }
}

// ---------------------------------------------------------------------------
extern "C" void kernel_launch(void* const* d_in, const int* in_sizes, int n_in,
                              void* d_out, int out_size) {
    const float* x        = (const float*)d_in[0];
    const float* gn_scale = (const float*)d_in[1];
    const float* gn_bias  = (const float*)d_in[2];
    const float* qkv_w    = (const float*)d_in[3];
    const float* qkv_b    = (const float*)d_in[4];
    const float* proj_w   = (const float*)d_in[5];
    const float* proj_b   = (const float*)d_in[6];
    const float* inl_w    = (const float*)d_in[7];
    const float* inl_b    = (const float*)d_in[8];
    float* out = (float*)d_out;

    const int attn_smem = (64*128 + 64*64 + 64*68 + 64*128) * 4;  // 99328 B
    cudaFuncSetAttribute(attn_kernel,
                         cudaFuncAttributeMaxDynamicSharedMemorySize, attn_smem);

    gn_kernel  <<<64, 1024>>>(x, gn_scale, gn_bias);
    qkv_kernel <<<dim3(8, 12, 8), 256>>>(qkv_w, qkv_b);
    attn_kernel<<<dim3(8, 64), 256, attn_smem>>>();
    inl_kernel <<<dim3(4, 64), 256>>>(0, inl_w, inl_b);   // f0 -> f1
    inl_kernel <<<dim3(4, 64), 256>>>(1, inl_w, inl_b);   // f1 -> f0
    inl_kernel <<<dim3(4, 64), 256>>>(0, inl_w, inl_b);   // f0 -> f1
    proj_kernel<<<dim3(8, 4, 8), 256>>>(proj_w, proj_b, x, out);
}

// round 7
// speedup vs baseline: 1.2041x; 1.0001x over previous
#include <cuda_runtime.h>

#define B_  8
#define C_  512
#define S_  1024
#define GS_ 8192      /* B_*S_ */
#define NH_ 8
#define HD_ 64

// All activations live in k-major [C][B*S] layout (col = b*1024 + s).
__device__ float g_h [C_*GS_];
__device__ float g_q [C_*GS_];
__device__ float g_k [C_*GS_];
__device__ float g_v [C_*GS_];
__device__ float g_f0[C_*GS_];
__device__ float g_f1[C_*GS_];
__device__ float g_wqkvT[C_*1536];   // [c][o], row stride 1536
__device__ float g_winlT[C_*C_];     // [c][o], row stride 512
__device__ float g_wprojT[C_*C_];    // [c][o], row stride 512

// ---------------------------------------------------------------------------
__device__ __forceinline__ void cpa16(void* s, const void* g) {
    unsigned a = (unsigned)__cvta_generic_to_shared(s);
    asm volatile("cp.async.cg.shared.global [%0], [%1], 16;" :: "r"(a), "l"(g));
}
#define CP_COMMIT() asm volatile("cp.async.commit_group;")
#define CP_WAIT0()  asm volatile("cp.async.wait_group 0;" ::: "memory")
__device__ __forceinline__ float tanh_a(float x) {
    float r; asm("tanh.approx.f32 %0, %1;" : "=f"(r) : "f"(x)); return r;
}

// ---------------------------------------------------------------------------
// Transpose: dst[c][r] = src[r][c].  src [R][512].  Destination is selected
// IN DEVICE CODE (passing a __device__ global's address from host gives the
// host shadow symbol, which ATS silently writes to host RAM — the R4-R6 bug).
// ---------------------------------------------------------------------------
__global__ void tr_kernel(const float* __restrict__ src, int which, int R) {
    float* dst = (which == 0) ? g_wqkvT : (which == 1) ? g_winlT : g_wprojT;
    __shared__ float t[32][33];
    int r0 = blockIdx.y * 32, c0 = blockIdx.x * 32;
    int x = threadIdx.x & 31, y = threadIdx.x >> 5;
    #pragma unroll
    for (int i = 0; i < 32; i += 8)
        t[y + i][x] = src[(r0 + y + i) * C_ + c0 + x];
    __syncthreads();
    #pragma unroll
    for (int i = 0; i < 32; i += 8)
        dst[(c0 + y + i) * R + r0 + x] = t[x][y + i];
}

// ---------------------------------------------------------------------------
// GroupNorm: 1 block (1024 thr) per (b, group). Writes k-major g_h[c][b*S+s].
// ---------------------------------------------------------------------------
__global__ void gn_kernel(const float* __restrict__ x,
                          const float* __restrict__ sc,
                          const float* __restrict__ bi) {
    int b = blockIdx.x >> 3, g = blockIdx.x & 7;
    int base = (b * C_ + g * 64) * S_;
    const float4* xp = (const float4*)(x + base);
    const int N4 = 64 * S_ / 4;   // 16384
    float s = 0.f, ss = 0.f;
    for (int i = threadIdx.x; i < N4; i += 1024) {
        float4 v = xp[i];
        s  += v.x + v.y + v.z + v.w;
        ss += v.x*v.x + v.y*v.y + v.z*v.z + v.w*v.w;
    }
    #pragma unroll
    for (int o = 16; o; o >>= 1) {
        s  += __shfl_xor_sync(0xffffffffu, s,  o);
        ss += __shfl_xor_sync(0xffffffffu, ss, o);
    }
    __shared__ float red[64];
    int wid = threadIdx.x >> 5;
    if ((threadIdx.x & 31) == 0) { red[wid] = s; red[32 + wid] = ss; }
    __syncthreads();
    if (threadIdx.x == 0) {
        float S = 0.f, SS = 0.f;
        #pragma unroll
        for (int w = 0; w < 32; w++) { S += red[w]; SS += red[32 + w]; }
        float mean = S * (1.f / 65536.f);
        float var  = SS * (1.f / 65536.f) - mean * mean;
        red[0] = mean; red[1] = rsqrtf(var + 1e-5f);
    }
    __syncthreads();
    float mean = red[0], inv = red[1];
    for (int i = threadIdx.x; i < N4; i += 1024) {
        int c = g * 64 + (i >> 8);
        float a = sc[c] * inv;
        float bb = bi[c] - mean * a;
        float4 v = xp[i];
        v.x = v.x*a + bb; v.y = v.y*a + bb; v.z = v.z*a + bb; v.w = v.w*a + bb;
        *(float4*)&g_h[c * GS_ + b * S_ + (i & 255) * 4] = v;
    }
}

// ===========================================================================
// TN SGEMM core: 128x128x16, cp.async double-buffered, 256 thr, 8x8 microtile.
// A,B both k-major: As[k][m] <- A[k][m0..], Bs[k][n] <- B[k][n0..] (direct cp).
// ===========================================================================
#define FMA16(bufc)                                                           \
    _Pragma("unroll")                                                         \
    for (int k = 0; k < 16; k++) {                                            \
        float4 a0 = *(const float4*)&As[bufc][k][ty*4];                       \
        float4 a1 = *(const float4*)&As[bufc][k][64 + ty*4];                  \
        float4 b0 = *(const float4*)&Bs[bufc][k][tx*4];                       \
        float4 b1 = *(const float4*)&Bs[bufc][k][64 + tx*4];                  \
        float av[8] = {a0.x,a0.y,a0.z,a0.w,a1.x,a1.y,a1.z,a1.w};              \
        float bw[8] = {b0.x,b0.y,b0.z,b0.w,b1.x,b1.y,b1.z,b1.w};              \
        _Pragma("unroll")                                                     \
        for (int ii = 0; ii < 8; ii++)                                        \
            _Pragma("unroll")                                                 \
            for (int jj = 0; jj < 8; jj++) acc[ii][jj] += av[ii] * bw[jj];    \
    }

#define FILL(bufc, k0, Ap, ldA, Bp, ldB)                                      \
    cpa16(&As[bufc][kr][fc],     (Ap) + (k0+kr)   * (ldA) + m0 + fc);         \
    cpa16(&As[bufc][kr+8][fc],   (Ap) + (k0+kr+8) * (ldA) + m0 + fc);         \
    cpa16(&Bs[bufc][kr][fc],     (Bp) + (k0+kr)   * (ldB) + n0 + fc);         \
    cpa16(&Bs[bufc][kr+8][fc],   (Bp) + (k0+kr+8) * (ldB) + n0 + fc);

#define GEMM_MAIN(Ap, ldA, Bp, ldB)                                           \
    FILL(0, 0, Ap, ldA, Bp, ldB); CP_COMMIT();                                \
    _Pragma("unroll 1")                                                       \
    for (int kt = 0; kt < 32; kt += 2) {                                      \
        CP_WAIT0(); __syncthreads();                                          \
        FILL(1, (kt+1)*16, Ap, ldA, Bp, ldB); CP_COMMIT();                    \
        FMA16(0);                                                             \
        CP_WAIT0(); __syncthreads();                                          \
        if (kt + 2 < 32) { FILL(0, (kt+2)*16, Ap, ldA, Bp, ldB); CP_COMMIT(); } \
        FMA16(1);                                                             \
    }

#define GEMM_PRELUDE                                                          \
    __shared__ float As[2][16][128], Bs[2][16][128];                          \
    int u = threadIdx.x, tx = u & 15, ty = u >> 4;                            \
    int kr = u >> 5, fc = (u & 31) * 4;                                       \
    int m0 = blockIdx.y * 128, n0 = blockIdx.x * 128;                         \
    float acc[8][8] = {};

// ---------------------------------------------------------------------------
// QKV: m=o (1536), n=gs (8192). A=g_wqkvT, B=g_h. Out -> g_q/g_k/g_v [c][gs].
// ---------------------------------------------------------------------------
__global__ __launch_bounds__(256, 2)
void qkv_kernel(const float* __restrict__ bias) {
    GEMM_PRELUDE
    GEMM_MAIN(g_wqkvT, 1536, g_h, GS_)
    #pragma unroll
    for (int i = 0; i < 8; i++) {
        int o = m0 + ((i & 4) ? 64 : 0) + ty * 4 + (i & 3);
        int sel = o >> 9;
        float* outp = ((sel == 0) ? g_q : (sel == 1) ? g_k : g_v)
                      + (o & 511) * GS_;
        float bv = bias[o];
        #pragma unroll
        for (int jg = 0; jg < 2; jg++) {
            int nn = n0 + jg * 64 + tx * 4;
            *(float4*)&outp[nn] = make_float4(acc[i][jg*4+0] + bv,
                                              acc[i][jg*4+1] + bv,
                                              acc[i][jg*4+2] + bv,
                                              acc[i][jg*4+3] + bv);
        }
    }
}

// ---------------------------------------------------------------------------
// INL: m=gs (8192), n=o (512). A=hin [c][gs], B=g_winlT [c][o].
// hout[o][gs] = hin[o][gs] + 0.1*tanh(acc + bias[o]).
// ---------------------------------------------------------------------------
__global__ __launch_bounds__(256, 2)
void inl_kernel(int flip, const float* __restrict__ bias) {
    const float* hin  = flip ? g_f1 : g_f0;
    float*       hout = flip ? g_f0 : g_f1;
    GEMM_PRELUDE
    GEMM_MAIN(hin, GS_, g_winlT, C_)
    float bvv[8];
    {
        float4 b0q = *(const float4*)&bias[n0 + tx * 4];
        float4 b1q = *(const float4*)&bias[n0 + 64 + tx * 4];
        bvv[0]=b0q.x; bvv[1]=b0q.y; bvv[2]=b0q.z; bvv[3]=b0q.w;
        bvv[4]=b1q.x; bvv[5]=b1q.y; bvv[6]=b1q.z; bvv[7]=b1q.w;
    }
    #pragma unroll
    for (int j = 0; j < 8; j++) {
        int o = n0 + ((j & 4) ? 64 : 0) + tx * 4 + (j & 3);
        float bo = bvv[j];
        #pragma unroll
        for (int ig = 0; ig < 2; ig++) {
            int mb = m0 + ig * 64 + ty * 4;
            float4 h = *(const float4*)&hin[o * GS_ + mb];
            h.x += 0.1f * tanh_a(acc[ig*4+0][j] + bo);
            h.y += 0.1f * tanh_a(acc[ig*4+1][j] + bo);
            h.z += 0.1f * tanh_a(acc[ig*4+2][j] + bo);
            h.w += 0.1f * tanh_a(acc[ig*4+3][j] + bo);
            *(float4*)&hout[o * GS_ + mb] = h;
        }
    }
}

// ---------------------------------------------------------------------------
// Proj + residual: m=o (512), n=gs (8192). A=g_wprojT, B=g_f1 (final INL).
// out[b][o][s] = x + bias[o] + acc.
// ---------------------------------------------------------------------------
__global__ __launch_bounds__(256, 2)
void proj_kernel(const float* __restrict__ bias, const float* __restrict__ x,
                 float* __restrict__ out) {
    GEMM_PRELUDE
    GEMM_MAIN(g_wprojT, C_, g_f1, GS_)
    #pragma unroll
    for (int i = 0; i < 8; i++) {
        int o = m0 + ((i & 4) ? 64 : 0) + ty * 4 + (i & 3);
        float pb = bias[o];
        #pragma unroll
        for (int jg = 0; jg < 2; jg++) {
            int gs = n0 + jg * 64 + tx * 4;
            int addr = ((gs >> 10) * C_ + o) * S_ + (gs & 1023);
            float4 xv = *(const float4*)&x[addr];
            *(float4*)&out[addr] = make_float4(acc[i][jg*4+0] + pb + xv.x,
                                               acc[i][jg*4+1] + pb + xv.y,
                                               acc[i][jg*4+2] + pb + xv.z,
                                               acc[i][jg*4+3] + pb + xv.w);
        }
    }
}

// ---------------------------------------------------------------------------
// Flash attention (R3-proven inner machinery, [c][gs] strides):
// block = (b, head) x 128-q tile, 256 threads. Plain loads, single K buffer,
// Vs pitch 68 unswizzled transpose, 3 barriers per tile.
// ---------------------------------------------------------------------------
__global__ __launch_bounds__(256, 2) void attn_kernel() {
    extern __shared__ float sm[];
    float* Qs = sm;                 // [64][128]   Qs[d][q]
    float* Ks = sm + 8192;          // [64][64]    Ks[d][t]
    float* Vs = sm + 12288;         // [64][68]    Vs[t][d] (pad 68)
    float* Ps = sm + 16640;         // [64][128]   Ps[t][q] swizzled
    int bn = blockIdx.y;
    int b = bn >> 3, n = bn & 7;
    const float* Qg = g_q + (n * HD_) * GS_ + b * S_;
    const float* Kg = g_k + (n * HD_) * GS_ + b * S_;
    const float* Vg = g_v + (n * HD_) * GS_ + b * S_;
    int q0 = blockIdx.x * 128;
    int u = threadIdx.x, tx = u & 15, ty = u >> 4;

    // Q prologue (scaled by hd^-0.5)
    #pragma unroll
    for (int r = 0; r < 8; r++) {
        int i = u + r * 256;
        int d = i >> 5, q4 = (i & 31) * 4;
        float4 q = *(const float4*)&Qg[d * GS_ + q0 + q4];
        q.x *= 0.125f; q.y *= 0.125f; q.z *= 0.125f; q.w *= 0.125f;
        *(float4*)&Qs[d * 128 + q4] = q;
    }
    float oa[8][4] = {};
    float m[8], l[8];
    #pragma unroll
    for (int i = 0; i < 8; i++) { m[i] = -1e30f; l[i] = 0.f; }

    #pragma unroll 1
    for (int t0 = 0; t0 < S_; t0 += 64) {
        __syncthreads();   // prev PV done with Vs/Ps; Q visible (1st iter)
        #pragma unroll
        for (int r = 0; r < 4; r++) {
            int i = u + r * 256;
            int d = i >> 4, t4 = (i & 15) * 4;
            *(float4*)&Ks[d * 64 + t4] = *(const float4*)&Kg[d * GS_ + t0 + t4];
            float4 v = *(const float4*)&Vg[d * GS_ + t0 + t4];
            Vs[(t4+0)*68 + d] = v.x; Vs[(t4+1)*68 + d] = v.y;
            Vs[(t4+2)*68 + d] = v.z; Vs[(t4+3)*68 + d] = v.w;
        }
        __syncthreads();

        // QK
        float s0[4][4] = {}, s1[4][4] = {};
        #pragma unroll 8
        for (int k = 0; k < 64; k++) {
            float4 a0 = *(const float4*)&Qs[k * 128 + ty * 4];
            float4 a1 = *(const float4*)&Qs[k * 128 + 64 + ty * 4];
            float4 bq = *(const float4*)&Ks[k * 64 + tx * 4];
            float av0[4] = {a0.x, a0.y, a0.z, a0.w};
            float av1[4] = {a1.x, a1.y, a1.z, a1.w};
            float bvv[4] = {bq.x, bq.y, bq.z, bq.w};
            #pragma unroll
            for (int i = 0; i < 4; i++)
                #pragma unroll
                for (int j = 0; j < 4; j++) {
                    s0[i][j] += av0[i] * bvv[j];
                    s1[i][j] += av1[i] * bvv[j];
                }
        }
        // online softmax
        float mloc[8], lloc[8];
        #pragma unroll
        for (int i = 0; i < 4; i++) {
            mloc[i]   = fmaxf(fmaxf(s0[i][0], s0[i][1]), fmaxf(s0[i][2], s0[i][3]));
            mloc[4+i] = fmaxf(fmaxf(s1[i][0], s1[i][1]), fmaxf(s1[i][2], s1[i][3]));
        }
        #pragma unroll
        for (int off = 1; off < 16; off <<= 1)
            #pragma unroll
            for (int i = 0; i < 8; i++)
                mloc[i] = fmaxf(mloc[i], __shfl_xor_sync(0xffffffffu, mloc[i], off));
        #pragma unroll
        for (int i = 0; i < 8; i++) {
            float mn = fmaxf(m[i], mloc[i]);
            float fac = __expf(m[i] - mn);
            m[i] = mn; l[i] *= fac;
            #pragma unroll
            for (int j = 0; j < 4; j++) oa[i][j] *= fac;
            float* srow = (i < 4) ? s0[i] : s1[i - 4];
            float a = 0.f;
            #pragma unroll
            for (int j = 0; j < 4; j++) { srow[j] = __expf(srow[j] - mn); a += srow[j]; }
            lloc[i] = a;
        }
        #pragma unroll
        for (int off = 1; off < 16; off <<= 1)
            #pragma unroll
            for (int i = 0; i < 8; i++)
                lloc[i] += __shfl_xor_sync(0xffffffffu, lloc[i], off);
        #pragma unroll
        for (int i = 0; i < 8; i++) l[i] += lloc[i];

        // store P transposed (swizzled): row t = tx*4+j, col group = (ty^tx)<<2
        #pragma unroll
        for (int j = 0; j < 4; j++) {
            int t = tx * 4 + j;
            int g0 = (ty ^ tx) << 2;
            *(float4*)&Ps[t * 128 + g0]      = make_float4(s0[0][j], s0[1][j], s0[2][j], s0[3][j]);
            *(float4*)&Ps[t * 128 + 64 + g0] = make_float4(s1[0][j], s1[1][j], s1[2][j], s1[3][j]);
        }
        __syncthreads();

        // PV
        #pragma unroll 8
        for (int k = 0; k < 64; k++) {
            int g = (ty ^ ((k >> 2) & 15)) << 2;
            float4 p0 = *(const float4*)&Ps[k * 128 + g];
            float4 p1 = *(const float4*)&Ps[k * 128 + 64 + g];
            float4 vv = *(const float4*)&Vs[k * 68 + tx * 4];
            float pv0[4] = {p0.x, p0.y, p0.z, p0.w};
            float pv1[4] = {p1.x, p1.y, p1.z, p1.w};
            float bvv[4] = {vv.x, vv.y, vv.z, vv.w};
            #pragma unroll
            for (int i = 0; i < 4; i++)
                #pragma unroll
                for (int j = 0; j < 4; j++) {
                    oa[i][j]   += pv0[i] * bvv[j];
                    oa[4+i][j] += pv1[i] * bvv[j];
                }
        }
    }
    // output: g_f0[c][gs], c = n*64+d, transposed store (float4 over q)
    float* outp = g_f0 + (n * HD_) * GS_ + b * S_ + q0;
    float inv[8];
    #pragma unroll
    for (int i = 0; i < 8; i++) inv[i] = 1.f / l[i];
    #pragma unroll
    for (int j = 0; j < 4; j++) {
        int d = tx * 4 + j;
        #pragma unroll
        for (int ig = 0; ig < 2; ig++) {
            int qb = ig * 64 + ty * 4;
            *(float4*)&outp[d * GS_ + qb] = make_float4(
                oa[ig*4+0][j] * inv[ig*4+0], oa[ig*4+1][j] * inv[ig*4+1],
                oa[ig*4+2][j] * inv[ig*4+2], oa[ig*4+3][j] * inv[ig*4+3]);
        }
    }
}

// ---------------------------------------------------------------------------
extern "C" void kernel_launch(void* const* d_in, const int* in_sizes, int n_in,
                              void* d_out, int out_size) {
    const float* x        = (const float*)d_in[0];
    const float* gn_scale = (const float*)d_in[1];
    const float* gn_bias  = (const float*)d_in[2];
    const float* qkv_w    = (const float*)d_in[3];
    const float* qkv_b    = (const float*)d_in[4];
    const float* proj_w   = (const float*)d_in[5];
    const float* proj_b   = (const float*)d_in[6];
    const float* inl_w    = (const float*)d_in[7];
    const float* inl_b    = (const float*)d_in[8];
    float* out = (float*)d_out;

    const int attn_smem = (8192 + 4096 + 64*68 + 8192) * 4;   // 99328 B
    cudaFuncSetAttribute(attn_kernel,
                         cudaFuncAttributeMaxDynamicSharedMemorySize, attn_smem);

    tr_kernel<<<dim3(16, 48), 256>>>(qkv_w,  0, 1536);
    tr_kernel<<<dim3(16, 16), 256>>>(inl_w,  1, 512);
    tr_kernel<<<dim3(16, 16), 256>>>(proj_w, 2, 512);
    gn_kernel<<<64, 1024>>>(x, gn_scale, gn_bias);
    qkv_kernel<<<dim3(64, 12), 256>>>(qkv_b);
    attn_kernel<<<dim3(8, 64), 256, attn_smem>>>();
    inl_kernel<<<dim3(4, 64), 256>>>(0, inl_b);   // f0 -> f1
    inl_kernel<<<dim3(4, 64), 256>>>(1, inl_b);   // f1 -> f0
    inl_kernel<<<dim3(4, 64), 256>>>(0, inl_b);   // f0 -> f1
    proj_kernel<<<dim3(64, 4), 256>>>(proj_b, x, out);
}

// round 9
// speedup vs baseline: 1.2780x; 1.0614x over previous
#include <cuda_runtime.h>
#include <cuda_bf16.h>
#include <cstdint>

#define B_  8
#define C_  512
#define S_  1024
#define GS_ 8192      /* B_*S_ */
#define NH_ 8
#define HD_ 64

// Activations: h/f0/f1 in [gs][c] (c contiguous); q/k/v in [c][gs] (gs contig).
__device__ float g_h [GS_*C_];
__device__ float g_q [C_*GS_];
__device__ float g_k [C_*GS_];
__device__ float g_v [C_*GS_];
__device__ float g_f0[GS_*C_];
__device__ float g_f1[GS_*C_];

__device__ __forceinline__ float tanh_a(float x) {
    float r; asm("tanh.approx.f32 %0, %1;" : "=f"(r) : "f"(x)); return r;
}

// Split one fp32 pair into bf16-hi pair + bf16-lo (residual) pair.
__device__ __forceinline__ void split2(float a, float b, uint32_t& hi, uint32_t& lo) {
    __nv_bfloat16 ha = __float2bfloat16_rn(a), hb = __float2bfloat16_rn(b);
    float ra = a - __bfloat162float(ha), rb = b - __bfloat162float(hb);
    __nv_bfloat162 H(ha, hb);
    __nv_bfloat162 L(__float2bfloat16_rn(ra), __float2bfloat16_rn(rb));
    hi = *reinterpret_cast<uint32_t*>(&H);
    lo = *reinterpret_cast<uint32_t*>(&L);
}

// m16n8k16 row.col f32 <- bf16 x bf16 + f32
#define MMA(d, a, b)                                                          \
    asm volatile("mma.sync.aligned.m16n8k16.row.col.f32.bf16.bf16.f32 "       \
        "{%0,%1,%2,%3}, {%4,%5,%6,%7}, {%8,%9}, {%0,%1,%2,%3};"               \
        : "+f"((d)[0]), "+f"((d)[1]), "+f"((d)[2]), "+f"((d)[3])              \
        : "r"((a)[0]), "r"((a)[1]), "r"((a)[2]), "r"((a)[3]),                 \
          "r"((b)[0]), "r"((b)[1]))

// ---------------------------------------------------------------------------
// GroupNorm -> g_h [gs][c] via smem-tiled transpose. 1 block / (b, group).
// ---------------------------------------------------------------------------
__global__ void gn_kernel(const float* __restrict__ x,
                          const float* __restrict__ sc,
                          const float* __restrict__ bi) {
    __shared__ float red[64];
    __shared__ float tile[64][65];
    int b = blockIdx.x >> 3, g = blockIdx.x & 7;
    int base = (b * C_ + g * 64) * S_;
    const float4* xp = (const float4*)(x + base);
    const int N4 = 64 * S_ / 4;
    float s = 0.f, ss = 0.f;
    for (int i = threadIdx.x; i < N4; i += 1024) {
        float4 v = xp[i];
        s  += v.x + v.y + v.z + v.w;
        ss += v.x*v.x + v.y*v.y + v.z*v.z + v.w*v.w;
    }
    #pragma unroll
    for (int o = 16; o; o >>= 1) {
        s  += __shfl_xor_sync(0xffffffffu, s,  o);
        ss += __shfl_xor_sync(0xffffffffu, ss, o);
    }
    int wid = threadIdx.x >> 5;
    if ((threadIdx.x & 31) == 0) { red[wid] = s; red[32 + wid] = ss; }
    __syncthreads();
    if (threadIdx.x == 0) {
        float S = 0.f, SS = 0.f;
        #pragma unroll
        for (int w = 0; w < 32; w++) { S += red[w]; SS += red[32 + w]; }
        float mean = S * (1.f / 65536.f);
        float var  = SS * (1.f / 65536.f) - mean * mean;
        red[0] = mean; red[1] = rsqrtf(var + 1e-5f);
    }
    __syncthreads();
    float mean = red[0], inv = red[1];
    int t = threadIdx.x;
    int r64 = t >> 4, q4 = (t & 15) * 4;       // load: channel row / s-quad
    float a  = sc[g * 64 + r64] * inv;
    float bb = bi[g * 64 + r64] - mean * a;
    for (int st = 0; st < 16; st++) {
        float4 v = *(const float4*)&x[base + r64 * S_ + st * 64 + q4];
        tile[r64][q4+0] = v.x*a + bb; tile[r64][q4+1] = v.y*a + bb;
        tile[r64][q4+2] = v.z*a + bb; tile[r64][q4+3] = v.w*a + bb;
        __syncthreads();
        int gs = b * S_ + st * 64 + r64;       // store: s row / c-quad
        float4 w = make_float4(tile[q4+0][r64], tile[q4+1][r64],
                               tile[q4+2][r64], tile[q4+3][r64]);
        *(float4*)&g_h[gs * C_ + g * 64 + q4] = w;
        __syncthreads();
    }
}

// ===========================================================================
// Split-bf16 HMMA GEMM core: D[128m x 128n] = A[m][k]·B[n][k], K=512.
// K chunked by 64 into smem bf16 hi/lo tiles, row pitch 72 bf16 (36 u32)
// -> conflict-free fragment LDS. 8 warps: warp tile 64x32 (4 mt x 4 nt).
// 3 HMMA passes per fragment pair: AhiBhi + AhiBlo + AloBhi (fp32 accum).
// ===========================================================================
#define MMSM (4 * 128 * 36 * 4)   /* 73728 B dynamic smem */

__device__ __forceinline__ void fill_split(uint32_t* hi, uint32_t* lo,
                                           const float* __restrict__ gsrc) {
    // 128 rows x 64 fp32 (row stride C_) -> hi/lo bf16 tiles
    int t = threadIdx.x, r = t >> 1, h = t & 1;
    const float* gr = gsrc + r * C_ + h * 32;
    uint32_t* hrow = hi + r * 36 + h * 16;
    uint32_t* lrow = lo + r * 36 + h * 16;
    #pragma unroll
    for (int i = 0; i < 4; i++) {
        float4 f0 = *(const float4*)(gr + i * 8);
        float4 f1 = *(const float4*)(gr + i * 8 + 4);
        uint4 H, L;
        split2(f0.x, f0.y, H.x, L.x);
        split2(f0.z, f0.w, H.y, L.y);
        split2(f1.x, f1.y, H.z, L.z);
        split2(f1.z, f1.w, H.w, L.w);
        *(uint4*)(hrow + i * 4) = H;
        *(uint4*)(lrow + i * 4) = L;
    }
}

#define MM_PRELUDE                                                            \
    extern __shared__ uint32_t smu[];                                         \
    uint32_t* Ahi = smu;                                                      \
    uint32_t* Alo = smu + 128*36;                                             \
    uint32_t* Bhi = smu + 2*128*36;                                           \
    uint32_t* Blo = smu + 3*128*36;                                           \
    int m0 = blockIdx.y * 128, n0 = blockIdx.x * 128;                         \
    int wid = threadIdx.x >> 5, lane = threadIdx.x & 31;                      \
    int gg = lane >> 2, tg = lane & 3;                                        \
    int wm = (wid & 1) * 64, wn = (wid >> 1) * 32;                            \
    float acc[4][4][4] = {};

#define MM_MAIN(Aptr, Bptr)                                                   \
    _Pragma("unroll 1")                                                       \
    for (int c = 0; c < 8; c++) {                                             \
        __syncthreads();                                                      \
        fill_split(Ahi, Alo, (Aptr) + m0 * C_ + c * 64);                      \
        fill_split(Bhi, Blo, (Bptr) + n0 * C_ + c * 64);                      \
        __syncthreads();                                                      \
        _Pragma("unroll")                                                     \
        for (int ks = 0; ks < 4; ks++) {                                      \
            uint32_t ah[4][4], al[4][4], bh[4][2], bl[4][2];                  \
            _Pragma("unroll")                                                 \
            for (int mt = 0; mt < 4; mt++) {                                  \
                int ba = (wm + mt*16 + gg) * 36 + ks * 8 + tg;                \
                ah[mt][0] = Ahi[ba];            al[mt][0] = Alo[ba];          \
                ah[mt][1] = Ahi[ba + 8*36];     al[mt][1] = Alo[ba + 8*36];   \
                ah[mt][2] = Ahi[ba + 4];        al[mt][2] = Alo[ba + 4];      \
                ah[mt][3] = Ahi[ba + 8*36 + 4]; al[mt][3] = Alo[ba + 8*36 + 4]; \
            }                                                                 \
            _Pragma("unroll")                                                 \
            for (int nt = 0; nt < 4; nt++) {                                  \
                int bb2 = (wn + nt*8 + gg) * 36 + ks * 8 + tg;                \
                bh[nt][0] = Bhi[bb2];     bl[nt][0] = Blo[bb2];               \
                bh[nt][1] = Bhi[bb2 + 4]; bl[nt][1] = Blo[bb2 + 4];           \
            }                                                                 \
            _Pragma("unroll")                                                 \
            for (int mt = 0; mt < 4; mt++)                                    \
                _Pragma("unroll")                                             \
                for (int nt = 0; nt < 4; nt++) {                              \
                    MMA(acc[mt][nt], ah[mt], bh[nt]);                         \
                    MMA(acc[mt][nt], ah[mt], bl[nt]);                         \
                    MMA(acc[mt][nt], al[mt], bh[nt]);                         \
                }                                                             \
        }                                                                     \
    }

// D frag mapping: c0=D[gg][2tg], c1=D[gg][2tg+1], c2=D[gg+8][2tg], c3=+1.

// ---------------------------------------------------------------------------
// QKV: A = qkv_w [o][c] (1536x512), B = g_h [gs][c]. D[o][gs] -> q/k/v [c][gs]
// ---------------------------------------------------------------------------
__global__ __launch_bounds__(256, 1)
void qkv_kernel(const float* __restrict__ W, const float* __restrict__ bias) {
    MM_PRELUDE
    MM_MAIN(W, g_h)
    int sel = m0 >> 9;
    float* outb = (sel == 0) ? g_q : (sel == 1) ? g_k : g_v;
    #pragma unroll
    for (int mt = 0; mt < 4; mt++) {
        int o = m0 + wm + mt*16 + gg;
        float bv0 = bias[o], bv1 = bias[o + 8];
        float* r0 = outb + (o & 511) * GS_ + n0;
        float* r1 = outb + ((o + 8) & 511) * GS_ + n0;
        #pragma unroll
        for (int nt = 0; nt < 4; nt++) {
            int col = wn + nt*8 + 2*tg;
            *(float2*)&r0[col] = make_float2(acc[mt][nt][0] + bv0,
                                             acc[mt][nt][1] + bv0);
            *(float2*)&r1[col] = make_float2(acc[mt][nt][2] + bv1,
                                             acc[mt][nt][3] + bv1);
        }
    }
}

// ---------------------------------------------------------------------------
// INL: A = hin [gs][c], B = inl_w [o][c]. D[gs][o].
// hout[gs][o] = hin[gs][o] + 0.1*tanh(acc + bias[o]).
// ---------------------------------------------------------------------------
__global__ __launch_bounds__(256, 1)
void inl_kernel(int flip, const float* __restrict__ W,
                const float* __restrict__ bias) {
    const float* hin  = flip ? g_f1 : g_f0;
    float*       hout = flip ? g_f0 : g_f1;
    MM_PRELUDE
    MM_MAIN(hin, W)
    #pragma unroll
    for (int mt = 0; mt < 4; mt++) {
        int gs0 = m0 + wm + mt*16 + gg;
        #pragma unroll
        for (int nt = 0; nt < 4; nt++) {
            int o = n0 + wn + nt*8 + 2*tg;
            float2 bq = *(const float2*)&bias[o];
            #pragma unroll
            for (int hh = 0; hh < 2; hh++) {
                int gs = gs0 + hh * 8;
                float2 hv = *(const float2*)&hin[gs * C_ + o];
                hv.x += 0.1f * tanh_a(acc[mt][nt][hh*2+0] + bq.x);
                hv.y += 0.1f * tanh_a(acc[mt][nt][hh*2+1] + bq.y);
                *(float2*)&hout[gs * C_ + o] = hv;
            }
        }
    }
}

// ---------------------------------------------------------------------------
// Proj: A = proj_w [o][c], B = g_f1 [gs][c]. D[o][gs].
// out[b][o][s] = x + bias[o] + acc.
// ---------------------------------------------------------------------------
__global__ __launch_bounds__(256, 1)
void proj_kernel(const float* __restrict__ W, const float* __restrict__ bias,
                 const float* __restrict__ x, float* __restrict__ out) {
    MM_PRELUDE
    MM_MAIN(W, g_f1)
    int b = n0 >> 10, sb = n0 & 1023;
    #pragma unroll
    for (int mt = 0; mt < 4; mt++) {
        #pragma unroll
        for (int hh = 0; hh < 2; hh++) {
            int o = m0 + wm + mt*16 + gg + hh * 8;
            float pb = bias[o];
            const float* xr = x + (b * C_ + o) * S_ + sb;
            float* orow = out + (b * C_ + o) * S_ + sb;
            #pragma unroll
            for (int nt = 0; nt < 4; nt++) {
                int col = wn + nt*8 + 2*tg;
                float2 xv = *(const float2*)&xr[col];
                *(float2*)&orow[col] =
                    make_float2(acc[mt][nt][hh*2+0] + pb + xv.x,
                                acc[mt][nt][hh*2+1] + pb + xv.y);
            }
        }
    }
}

// ---------------------------------------------------------------------------
// Flash attention (SIMT, R7-proven body). q/k/v [c][gs] in; g_f0 [gs][c] out.
// ---------------------------------------------------------------------------
__global__ __launch_bounds__(256, 2) void attn_kernel() {
    extern __shared__ float smf[];
    float* Qs = smf;                // [64][128]
    float* Ks = smf + 8192;         // [64][64]
    float* Vs = smf + 12288;        // [64][68]
    float* Ps = smf + 16640;        // [64][128] swizzled
    int bn = blockIdx.y;
    int b = bn >> 3, n = bn & 7;
    const float* Qg = g_q + (n * HD_) * GS_ + b * S_;
    const float* Kg = g_k + (n * HD_) * GS_ + b * S_;
    const float* Vg = g_v + (n * HD_) * GS_ + b * S_;
    int q0 = blockIdx.x * 128;
    int u = threadIdx.x, tx = u & 15, ty = u >> 4;

    #pragma unroll
    for (int r = 0; r < 8; r++) {
        int i = u + r * 256;
        int d = i >> 5, q4 = (i & 31) * 4;
        float4 q = *(const float4*)&Qg[d * GS_ + q0 + q4];
        q.x *= 0.125f; q.y *= 0.125f; q.z *= 0.125f; q.w *= 0.125f;
        *(float4*)&Qs[d * 128 + q4] = q;
    }
    float oa[8][4] = {};
    float m[8], l[8];
    #pragma unroll
    for (int i = 0; i < 8; i++) { m[i] = -1e30f; l[i] = 0.f; }

    #pragma unroll 1
    for (int t0 = 0; t0 < S_; t0 += 64) {
        __syncthreads();
        #pragma unroll
        for (int r = 0; r < 4; r++) {
            int i = u + r * 256;
            int d = i >> 4, t4 = (i & 15) * 4;
            *(float4*)&Ks[d * 64 + t4] = *(const float4*)&Kg[d * GS_ + t0 + t4];
            float4 v = *(const float4*)&Vg[d * GS_ + t0 + t4];
            Vs[(t4+0)*68 + d] = v.x; Vs[(t4+1)*68 + d] = v.y;
            Vs[(t4+2)*68 + d] = v.z; Vs[(t4+3)*68 + d] = v.w;
        }
        __syncthreads();

        float s0[4][4] = {}, s1[4][4] = {};
        #pragma unroll 8
        for (int k = 0; k < 64; k++) {
            float4 a0 = *(const float4*)&Qs[k * 128 + ty * 4];
            float4 a1 = *(const float4*)&Qs[k * 128 + 64 + ty * 4];
            float4 bq = *(const float4*)&Ks[k * 64 + tx * 4];
            float av0[4] = {a0.x, a0.y, a0.z, a0.w};
            float av1[4] = {a1.x, a1.y, a1.z, a1.w};
            float bvv[4] = {bq.x, bq.y, bq.z, bq.w};
            #pragma unroll
            for (int i = 0; i < 4; i++)
                #pragma unroll
                for (int j = 0; j < 4; j++) {
                    s0[i][j] += av0[i] * bvv[j];
                    s1[i][j] += av1[i] * bvv[j];
                }
        }
        float mloc[8], lloc[8];
        #pragma unroll
        for (int i = 0; i < 4; i++) {
            mloc[i]   = fmaxf(fmaxf(s0[i][0], s0[i][1]), fmaxf(s0[i][2], s0[i][3]));
            mloc[4+i] = fmaxf(fmaxf(s1[i][0], s1[i][1]), fmaxf(s1[i][2], s1[i][3]));
        }
        #pragma unroll
        for (int off = 1; off < 16; off <<= 1)
            #pragma unroll
            for (int i = 0; i < 8; i++)
                mloc[i] = fmaxf(mloc[i], __shfl_xor_sync(0xffffffffu, mloc[i], off));
        #pragma unroll
        for (int i = 0; i < 8; i++) {
            float mn = fmaxf(m[i], mloc[i]);
            float fac = __expf(m[i] - mn);
            m[i] = mn; l[i] *= fac;
            #pragma unroll
            for (int j = 0; j < 4; j++) oa[i][j] *= fac;
            float* srow = (i < 4) ? s0[i] : s1[i - 4];
            float a = 0.f;
            #pragma unroll
            for (int j = 0; j < 4; j++) { srow[j] = __expf(srow[j] - mn); a += srow[j]; }
            lloc[i] = a;
        }
        #pragma unroll
        for (int off = 1; off < 16; off <<= 1)
            #pragma unroll
            for (int i = 0; i < 8; i++)
                lloc[i] += __shfl_xor_sync(0xffffffffu, lloc[i], off);
        #pragma unroll
        for (int i = 0; i < 8; i++) l[i] += lloc[i];

        #pragma unroll
        for (int j = 0; j < 4; j++) {
            int t = tx * 4 + j;
            int g0 = (ty ^ tx) << 2;
            *(float4*)&Ps[t * 128 + g0]      = make_float4(s0[0][j], s0[1][j], s0[2][j], s0[3][j]);
            *(float4*)&Ps[t * 128 + 64 + g0] = make_float4(s1[0][j], s1[1][j], s1[2][j], s1[3][j]);
        }
        __syncthreads();

        #pragma unroll 8
        for (int k = 0; k < 64; k++) {
            int g = (ty ^ ((k >> 2) & 15)) << 2;
            float4 p0 = *(const float4*)&Ps[k * 128 + g];
            float4 p1 = *(const float4*)&Ps[k * 128 + 64 + g];
            float4 vv = *(const float4*)&Vs[k * 68 + tx * 4];
            float pv0[4] = {p0.x, p0.y, p0.z, p0.w};
            float pv1[4] = {p1.x, p1.y, p1.z, p1.w};
            float bvv[4] = {vv.x, vv.y, vv.z, vv.w};
            #pragma unroll
            for (int i = 0; i < 4; i++)
                #pragma unroll
                for (int j = 0; j < 4; j++) {
                    oa[i][j]   += pv0[i] * bvv[j];
                    oa[4+i][j] += pv1[i] * bvv[j];
                }
        }
    }
    float* outp = g_f0 + (b * S_ + q0) * C_ + n * HD_;
    #pragma unroll
    for (int i = 0; i < 8; i++) {
        int q = ((i & 4) ? 64 : 0) + ty * 4 + (i & 3);
        float inv = 1.f / l[i];
        *(float4*)&outp[q * C_ + tx * 4] =
            make_float4(oa[i][0]*inv, oa[i][1]*inv, oa[i][2]*inv, oa[i][3]*inv);
    }
}

// ---------------------------------------------------------------------------
extern "C" void kernel_launch(void* const* d_in, const int* in_sizes, int n_in,
                              void* d_out, int out_size) {
    const float* x        = (const float*)d_in[0];
    const float* gn_scale = (const float*)d_in[1];
    const float* gn_bias  = (const float*)d_in[2];
    const float* qkv_w    = (const float*)d_in[3];
    const float* qkv_b    = (const float*)d_in[4];
    const float* proj_w   = (const float*)d_in[5];
    const float* proj_b   = (const float*)d_in[6];
    const float* inl_w    = (const float*)d_in[7];
    const float* inl_b    = (const float*)d_in[8];
    float* out = (float*)d_out;

    const int attn_smem = (8192 + 4096 + 64*68 + 8192) * 4;   // 99328 B
    cudaFuncSetAttribute(attn_kernel,
                         cudaFuncAttributeMaxDynamicSharedMemorySize, attn_smem);
    cudaFuncSetAttribute(qkv_kernel,
                         cudaFuncAttributeMaxDynamicSharedMemorySize, MMSM);
    cudaFuncSetAttribute(inl_kernel,
                         cudaFuncAttributeMaxDynamicSharedMemorySize, MMSM);
    cudaFuncSetAttribute(proj_kernel,
                         cudaFuncAttributeMaxDynamicSharedMemorySize, MMSM);

    gn_kernel <<<64, 1024>>>(x, gn_scale, gn_bias);
    qkv_kernel<<<dim3(64, 12), 256, MMSM>>>(qkv_w, qkv_b);
    attn_kernel<<<dim3(8, 64), 256, attn_smem>>>();
    inl_kernel<<<dim3(4, 64), 256, MMSM>>>(0, inl_w, inl_b);   // f0 -> f1
    inl_kernel<<<dim3(4, 64), 256, MMSM>>>(1, inl_w, inl_b);   // f1 -> f0
    inl_kernel<<<dim3(4, 64), 256, MMSM>>>(0, inl_w, inl_b);   // f0 -> f1
    proj_kernel<<<dim3(64, 4), 256, MMSM>>>(proj_w, proj_b, x, out);
}

// round 10
// speedup vs baseline: 1.4249x; 1.1150x over previous
#include <cuda_runtime.h>
#include <cuda_bf16.h>
#include <cstdint>

#define B_  8
#define C_  512
#define S_  1024
#define GS_ 8192      /* B_*S_ */
#define NH_ 8
#define HD_ 64

// fp32 activations
__device__ float g_q [C_*GS_];
__device__ float g_k [C_*GS_];
__device__ float g_v [C_*GS_];
__device__ float g_f0[GS_*C_];
__device__ float g_f1[GS_*C_];
// bf16 hi/lo operand planes for tensor-core GEMMs (all [row][c], c contiguous)
__device__ __nv_bfloat16 g_hh [GS_*C_], g_hl [GS_*C_];
__device__ __nv_bfloat16 g_a0h[GS_*C_], g_a0l[GS_*C_];
__device__ __nv_bfloat16 g_a1h[GS_*C_], g_a1l[GS_*C_];
__device__ __nv_bfloat16 g_wqh[1536*C_], g_wql[1536*C_];
__device__ __nv_bfloat16 g_wih[C_*C_],   g_wil[C_*C_];
__device__ __nv_bfloat16 g_wph[C_*C_],   g_wpl[C_*C_];

// ---------------------------------------------------------------------------
__device__ __forceinline__ void cpa16(void* s, const void* g) {
    unsigned a = (unsigned)__cvta_generic_to_shared(s);
    asm volatile("cp.async.cg.shared.global [%0], [%1], 16;" :: "r"(a), "l"(g));
}
#define CP_COMMIT() asm volatile("cp.async.commit_group;")
__device__ __forceinline__ float tanh_a(float x) {
    float r; asm("tanh.approx.f32 %0, %1;" : "=f"(r) : "f"(x)); return r;
}
// Split fp32 pair -> packed bf16-hi pair + bf16-lo (residual) pair.
__device__ __forceinline__ void split2(float a, float b, uint32_t& hi, uint32_t& lo) {
    __nv_bfloat16 ha = __float2bfloat16_rn(a), hb = __float2bfloat16_rn(b);
    float ra = a - __bfloat162float(ha), rb = b - __bfloat162float(hb);
    __nv_bfloat162 H(ha, hb);
    __nv_bfloat162 L(__float2bfloat16_rn(ra), __float2bfloat16_rn(rb));
    hi = *reinterpret_cast<uint32_t*>(&H);
    lo = *reinterpret_cast<uint32_t*>(&L);
}
// m16n8k16 row.col f32 <- bf16 x bf16 + f32
#define MMA(d, a, b)                                                          \
    asm volatile("mma.sync.aligned.m16n8k16.row.col.f32.bf16.bf16.f32 "       \
        "{%0,%1,%2,%3}, {%4,%5,%6,%7}, {%8,%9}, {%0,%1,%2,%3};"               \
        : "+f"((d)[0]), "+f"((d)[1]), "+f"((d)[2]), "+f"((d)[3])              \
        : "r"((a)[0]), "r"((a)[1]), "r"((a)[2]), "r"((a)[3]),                 \
          "r"((b)[0]), "r"((b)[1]))

// ---------------------------------------------------------------------------
// Weight fp32 -> bf16 hi/lo planes. Destination chosen in device code.
// ---------------------------------------------------------------------------
__global__ void convw_kernel(const float* __restrict__ src, int which) {
    __nv_bfloat16 *dh, *dl;
    if (which == 0)      { dh = g_wqh; dl = g_wql; }
    else if (which == 1) { dh = g_wih; dl = g_wil; }
    else                 { dh = g_wph; dl = g_wpl; }
    int i = blockIdx.x * 256 + threadIdx.x;
    float4 v = *(const float4*)&src[i * 4];
    uint32_t h0, l0, h1, l1;
    split2(v.x, v.y, h0, l0);
    split2(v.z, v.w, h1, l1);
    *(uint2*)&dh[i * 4] = make_uint2(h0, h1);
    *(uint2*)&dl[i * 4] = make_uint2(l0, l1);
}

// ---------------------------------------------------------------------------
// GroupNorm -> bf16 hi/lo planes g_hh/g_hl in [gs][c] (via smem transpose).
// ---------------------------------------------------------------------------
__global__ void gn_kernel(const float* __restrict__ x,
                          const float* __restrict__ sc,
                          const float* __restrict__ bi) {
    __shared__ float red[64];
    __shared__ float tile[64][65];
    int b = blockIdx.x >> 3, g = blockIdx.x & 7;
    int base = (b * C_ + g * 64) * S_;
    const float4* xp = (const float4*)(x + base);
    const int N4 = 64 * S_ / 4;
    float s = 0.f, ss = 0.f;
    for (int i = threadIdx.x; i < N4; i += 1024) {
        float4 v = xp[i];
        s  += v.x + v.y + v.z + v.w;
        ss += v.x*v.x + v.y*v.y + v.z*v.z + v.w*v.w;
    }
    #pragma unroll
    for (int o = 16; o; o >>= 1) {
        s  += __shfl_xor_sync(0xffffffffu, s,  o);
        ss += __shfl_xor_sync(0xffffffffu, ss, o);
    }
    int wid = threadIdx.x >> 5;
    if ((threadIdx.x & 31) == 0) { red[wid] = s; red[32 + wid] = ss; }
    __syncthreads();
    if (threadIdx.x == 0) {
        float S = 0.f, SS = 0.f;
        #pragma unroll
        for (int w = 0; w < 32; w++) { S += red[w]; SS += red[32 + w]; }
        float mean = S * (1.f / 65536.f);
        float var  = SS * (1.f / 65536.f) - mean * mean;
        red[0] = mean; red[1] = rsqrtf(var + 1e-5f);
    }
    __syncthreads();
    float mean = red[0], inv = red[1];
    int t = threadIdx.x;
    int r64 = t >> 4, q4 = (t & 15) * 4;
    float a  = sc[g * 64 + r64] * inv;
    float bb = bi[g * 64 + r64] - mean * a;
    for (int st = 0; st < 16; st++) {
        float4 v = *(const float4*)&x[base + r64 * S_ + st * 64 + q4];
        tile[r64][q4+0] = v.x*a + bb; tile[r64][q4+1] = v.y*a + bb;
        tile[r64][q4+2] = v.z*a + bb; tile[r64][q4+3] = v.w*a + bb;
        __syncthreads();
        int gs = b * S_ + st * 64 + r64;
        float4 w = make_float4(tile[q4+0][r64], tile[q4+1][r64],
                               tile[q4+2][r64], tile[q4+3][r64]);
        int idx = gs * C_ + g * 64 + q4;
        uint32_t h0, l0, h1, l1;
        split2(w.x, w.y, h0, l0);
        split2(w.z, w.w, h1, l1);
        *(uint2*)&g_hh[idx] = make_uint2(h0, h1);
        *(uint2*)&g_hl[idx] = make_uint2(l0, l1);
        __syncthreads();
    }
}

// ===========================================================================
// Split-bf16 HMMA GEMM: D[128m x 128n] = A·B^T, K=512 in 8 chunks of 64,
// operand planes pre-converted bf16 in global; cp.async double-buffered into
// padded pitch-36(u32) smem (R9-proven fragment addressing). 8 warps,
// warp tile 64x32 (4mt x 4nt m16n8k16), 3 passes: AhBh + AhBl + AlBh.
// ===========================================================================
#define PITCH_U32  36
#define PLANE_B    (128 * PITCH_U32 * 4)   /* 18432 */
#define BUF_B      (4 * PLANE_B)           /* 73728 */
#define MMSM       (2 * BUF_B)             /* 147456 */

__device__ __forceinline__ void fill_chunk(char* buf,
        const __nv_bfloat16* __restrict__ Ah, const __nv_bfloat16* __restrict__ Al,
        const __nv_bfloat16* __restrict__ Bh, const __nv_bfloat16* __restrict__ Bl,
        int m0, int n0, int ch) {
    int t = threadIdx.x, row = t >> 1, sb = (t & 1) * 4;
    int aoff = (m0 + row) * C_ + ch * 64 + sb * 8;
    int boff = (n0 + row) * C_ + ch * 64 + sb * 8;
    char* d0 = buf + row * 144 + sb * 16;
    #pragma unroll
    for (int i = 0; i < 4; i++) {
        cpa16(d0 +             i * 16, Ah + aoff + i * 8);
        cpa16(d0 + PLANE_B   + i * 16, Al + aoff + i * 8);
        cpa16(d0 + 2*PLANE_B + i * 16, Bh + boff + i * 8);
        cpa16(d0 + 3*PLANE_B + i * 16, Bl + boff + i * 8);
    }
}

#define MM_PRELUDE                                                            \
    extern __shared__ char smc[];                                             \
    int m0 = blockIdx.y * 128, n0 = blockIdx.x * 128;                         \
    int wid = threadIdx.x >> 5, lane = threadIdx.x & 31;                      \
    int gg = lane >> 2, tg = lane & 3;                                        \
    int wm = (wid & 1) * 64, wn = (wid >> 1) * 32;                            \
    float acc[4][4][4] = {};

#define MM_MAIN(AhP, AlP, BhP, BlP)                                           \
    fill_chunk(smc, AhP, AlP, BhP, BlP, m0, n0, 0); CP_COMMIT();              \
    _Pragma("unroll 1")                                                       \
    for (int c = 0; c < 8; c++) {                                             \
        if (c + 1 < 8) {                                                      \
            fill_chunk(smc + ((c+1)&1)*BUF_B, AhP, AlP, BhP, BlP, m0, n0, c+1);\
            CP_COMMIT();                                                      \
            asm volatile("cp.async.wait_group 1;" ::: "memory");              \
        } else {                                                              \
            asm volatile("cp.async.wait_group 0;" ::: "memory");              \
        }                                                                     \
        __syncthreads();                                                      \
        uint32_t* Ahi = (uint32_t*)(smc + (c&1)*BUF_B);                       \
        uint32_t* Alo = Ahi + 128*PITCH_U32;                                  \
        uint32_t* Bhi = Ahi + 2*128*PITCH_U32;                                \
        uint32_t* Blo = Ahi + 3*128*PITCH_U32;                                \
        _Pragma("unroll")                                                     \
        for (int ks = 0; ks < 4; ks++) {                                      \
            uint32_t ah[4][4], al[4][4], bh[4][2], bl[4][2];                  \
            _Pragma("unroll")                                                 \
            for (int mt = 0; mt < 4; mt++) {                                  \
                int ba = (wm + mt*16 + gg) * 36 + ks * 8 + tg;                \
                ah[mt][0] = Ahi[ba];            al[mt][0] = Alo[ba];          \
                ah[mt][1] = Ahi[ba + 8*36];     al[mt][1] = Alo[ba + 8*36];   \
                ah[mt][2] = Ahi[ba + 4];        al[mt][2] = Alo[ba + 4];      \
                ah[mt][3] = Ahi[ba + 8*36 + 4]; al[mt][3] = Alo[ba + 8*36 + 4]; \
            }                                                                 \
            _Pragma("unroll")                                                 \
            for (int nt = 0; nt < 4; nt++) {                                  \
                int bb2 = (wn + nt*8 + gg) * 36 + ks * 8 + tg;                \
                bh[nt][0] = Bhi[bb2];     bl[nt][0] = Blo[bb2];               \
                bh[nt][1] = Bhi[bb2 + 4]; bl[nt][1] = Blo[bb2 + 4];           \
            }                                                                 \
            _Pragma("unroll")                                                 \
            for (int mt = 0; mt < 4; mt++)                                    \
                _Pragma("unroll")                                             \
                for (int nt = 0; nt < 4; nt++) {                              \
                    MMA(acc[mt][nt], ah[mt], bh[nt]);                         \
                    MMA(acc[mt][nt], ah[mt], bl[nt]);                         \
                    MMA(acc[mt][nt], al[mt], bh[nt]);                         \
                }                                                             \
        }                                                                     \
        __syncthreads();                                                      \
    }

// D frag mapping: c0=D[gg][2tg], c1=D[gg][2tg+1], c2=D[gg+8][2tg], c3=+1.

// ---------------------------------------------------------------------------
// QKV: A = wqkv planes [o][c] (m=1536), B = g_h planes [gs][c]. -> q/k/v fp32
// ---------------------------------------------------------------------------
__global__ __launch_bounds__(256, 1)
void qkv_kernel(const float* __restrict__ bias) {
    MM_PRELUDE
    MM_MAIN(g_wqh, g_wql, g_hh, g_hl)
    int sel = m0 >> 9;
    float* outb = (sel == 0) ? g_q : (sel == 1) ? g_k : g_v;
    #pragma unroll
    for (int mt = 0; mt < 4; mt++) {
        int o = m0 + wm + mt*16 + gg;
        float bv0 = bias[o], bv1 = bias[o + 8];
        float* r0 = outb + (o & 511) * GS_ + n0;
        float* r1 = outb + ((o + 8) & 511) * GS_ + n0;
        #pragma unroll
        for (int nt = 0; nt < 4; nt++) {
            int col = wn + nt*8 + 2*tg;
            *(float2*)&r0[col] = make_float2(acc[mt][nt][0] + bv0,
                                             acc[mt][nt][1] + bv0);
            *(float2*)&r1[col] = make_float2(acc[mt][nt][2] + bv1,
                                             acc[mt][nt][3] + bv1);
        }
    }
}

// ---------------------------------------------------------------------------
// INL: A = activation planes (a0/a1 by flip), B = winl planes. D[gs][o].
// hout = hin + 0.1*tanh(acc + bias); writes fp32 hout + next planes.
// ---------------------------------------------------------------------------
__global__ __launch_bounds__(256, 1)
void inl_kernel(int flip, const float* __restrict__ bias) {
    const __nv_bfloat16* Ah = flip ? g_a1h : g_a0h;
    const __nv_bfloat16* Al = flip ? g_a1l : g_a0l;
    __nv_bfloat16* Oh = flip ? g_a0h : g_a1h;
    __nv_bfloat16* Ol = flip ? g_a0l : g_a1l;
    const float* hin  = flip ? g_f1 : g_f0;
    float*       hout = flip ? g_f0 : g_f1;
    MM_PRELUDE
    MM_MAIN(Ah, Al, g_wih, g_wil)
    #pragma unroll
    for (int mt = 0; mt < 4; mt++) {
        int gs0 = m0 + wm + mt*16 + gg;
        #pragma unroll
        for (int nt = 0; nt < 4; nt++) {
            int o = n0 + wn + nt*8 + 2*tg;
            float2 bq = *(const float2*)&bias[o];
            #pragma unroll
            for (int hh = 0; hh < 2; hh++) {
                int gs = gs0 + hh * 8;
                float2 hv = *(const float2*)&hin[gs * C_ + o];
                hv.x += 0.1f * tanh_a(acc[mt][nt][hh*2+0] + bq.x);
                hv.y += 0.1f * tanh_a(acc[mt][nt][hh*2+1] + bq.y);
                *(float2*)&hout[gs * C_ + o] = hv;
                uint32_t hb, lb;
                split2(hv.x, hv.y, hb, lb);
                *(uint32_t*)&Oh[gs * C_ + o] = hb;
                *(uint32_t*)&Ol[gs * C_ + o] = lb;
            }
        }
    }
}

// ---------------------------------------------------------------------------
// Proj: A = wproj planes [o][c], B = a1 planes (final INL). + x residual.
// ---------------------------------------------------------------------------
__global__ __launch_bounds__(256, 1)
void proj_kernel(const float* __restrict__ bias, const float* __restrict__ x,
                 float* __restrict__ out) {
    MM_PRELUDE
    MM_MAIN(g_wph, g_wpl, g_a1h, g_a1l)
    int b = n0 >> 10, sb = n0 & 1023;
    #pragma unroll
    for (int mt = 0; mt < 4; mt++) {
        #pragma unroll
        for (int hh = 0; hh < 2; hh++) {
            int o = m0 + wm + mt*16 + gg + hh * 8;
            float pb = bias[o];
            const float* xr = x + (b * C_ + o) * S_ + sb;
            float* orow = out + (b * C_ + o) * S_ + sb;
            #pragma unroll
            for (int nt = 0; nt < 4; nt++) {
                int col = wn + nt*8 + 2*tg;
                float2 xv = *(const float2*)&xr[col];
                *(float2*)&orow[col] =
                    make_float2(acc[mt][nt][hh*2+0] + pb + xv.x,
                                acc[mt][nt][hh*2+1] + pb + xv.y);
            }
        }
    }
}

// ---------------------------------------------------------------------------
// Flash attention (SIMT, R7/R9-proven body). q/k/v [c][gs] in;
// out: g_f0 fp32 [gs][c] + a0 bf16 planes.
// ---------------------------------------------------------------------------
__global__ __launch_bounds__(256, 2) void attn_kernel() {
    extern __shared__ float smf[];
    float* Qs = smf;                // [64][128]
    float* Ks = smf + 8192;         // [64][64]
    float* Vs = smf + 12288;        // [64][68]
    float* Ps = smf + 16640;        // [64][128] swizzled
    int bn = blockIdx.y;
    int b = bn >> 3, n = bn & 7;
    const float* Qg = g_q + (n * HD_) * GS_ + b * S_;
    const float* Kg = g_k + (n * HD_) * GS_ + b * S_;
    const float* Vg = g_v + (n * HD_) * GS_ + b * S_;
    int q0 = blockIdx.x * 128;
    int u = threadIdx.x, tx = u & 15, ty = u >> 4;

    #pragma unroll
    for (int r = 0; r < 8; r++) {
        int i = u + r * 256;
        int d = i >> 5, q4 = (i & 31) * 4;
        float4 q = *(const float4*)&Qg[d * GS_ + q0 + q4];
        q.x *= 0.125f; q.y *= 0.125f; q.z *= 0.125f; q.w *= 0.125f;
        *(float4*)&Qs[d * 128 + q4] = q;
    }
    float oa[8][4] = {};
    float m[8], l[8];
    #pragma unroll
    for (int i = 0; i < 8; i++) { m[i] = -1e30f; l[i] = 0.f; }

    #pragma unroll 1
    for (int t0 = 0; t0 < S_; t0 += 64) {
        __syncthreads();
        #pragma unroll
        for (int r = 0; r < 4; r++) {
            int i = u + r * 256;
            int d = i >> 4, t4 = (i & 15) * 4;
            *(float4*)&Ks[d * 64 + t4] = *(const float4*)&Kg[d * GS_ + t0 + t4];
            float4 v = *(const float4*)&Vg[d * GS_ + t0 + t4];
            Vs[(t4+0)*68 + d] = v.x; Vs[(t4+1)*68 + d] = v.y;
            Vs[(t4+2)*68 + d] = v.z; Vs[(t4+3)*68 + d] = v.w;
        }
        __syncthreads();

        float s0[4][4] = {}, s1[4][4] = {};
        #pragma unroll 8
        for (int k = 0; k < 64; k++) {
            float4 a0 = *(const float4*)&Qs[k * 128 + ty * 4];
            float4 a1 = *(const float4*)&Qs[k * 128 + 64 + ty * 4];
            float4 bq = *(const float4*)&Ks[k * 64 + tx * 4];
            float av0[4] = {a0.x, a0.y, a0.z, a0.w};
            float av1[4] = {a1.x, a1.y, a1.z, a1.w};
            float bvv[4] = {bq.x, bq.y, bq.z, bq.w};
            #pragma unroll
            for (int i = 0; i < 4; i++)
                #pragma unroll
                for (int j = 0; j < 4; j++) {
                    s0[i][j] += av0[i] * bvv[j];
                    s1[i][j] += av1[i] * bvv[j];
                }
        }
        float mloc[8], lloc[8];
        #pragma unroll
        for (int i = 0; i < 4; i++) {
            mloc[i]   = fmaxf(fmaxf(s0[i][0], s0[i][1]), fmaxf(s0[i][2], s0[i][3]));
            mloc[4+i] = fmaxf(fmaxf(s1[i][0], s1[i][1]), fmaxf(s1[i][2], s1[i][3]));
        }
        #pragma unroll
        for (int off = 1; off < 16; off <<= 1)
            #pragma unroll
            for (int i = 0; i < 8; i++)
                mloc[i] = fmaxf(mloc[i], __shfl_xor_sync(0xffffffffu, mloc[i], off));
        #pragma unroll
        for (int i = 0; i < 8; i++) {
            float mn = fmaxf(m[i], mloc[i]);
            float fac = __expf(m[i] - mn);
            m[i] = mn; l[i] *= fac;
            #pragma unroll
            for (int j = 0; j < 4; j++) oa[i][j] *= fac;
            float* srow = (i < 4) ? s0[i] : s1[i - 4];
            float a = 0.f;
            #pragma unroll
            for (int j = 0; j < 4; j++) { srow[j] = __expf(srow[j] - mn); a += srow[j]; }
            lloc[i] = a;
        }
        #pragma unroll
        for (int off = 1; off < 16; off <<= 1)
            #pragma unroll
            for (int i = 0; i < 8; i++)
                lloc[i] += __shfl_xor_sync(0xffffffffu, lloc[i], off);
        #pragma unroll
        for (int i = 0; i < 8; i++) l[i] += lloc[i];

        #pragma unroll
        for (int j = 0; j < 4; j++) {
            int t = tx * 4 + j;
            int g0 = (ty ^ tx) << 2;
            *(float4*)&Ps[t * 128 + g0]      = make_float4(s0[0][j], s0[1][j], s0[2][j], s0[3][j]);
            *(float4*)&Ps[t * 128 + 64 + g0] = make_float4(s1[0][j], s1[1][j], s1[2][j], s1[3][j]);
        }
        __syncthreads();

        #pragma unroll 8
        for (int k = 0; k < 64; k++) {
            int g = (ty ^ ((k >> 2) & 15)) << 2;
            float4 p0 = *(const float4*)&Ps[k * 128 + g];
            float4 p1 = *(const float4*)&Ps[k * 128 + 64 + g];
            float4 vv = *(const float4*)&Vs[k * 68 + tx * 4];
            float pv0[4] = {p0.x, p0.y, p0.z, p0.w};
            float pv1[4] = {p1.x, p1.y, p1.z, p1.w};
            float bvv[4] = {vv.x, vv.y, vv.z, vv.w};
            #pragma unroll
            for (int i = 0; i < 4; i++)
                #pragma unroll
                for (int j = 0; j < 4; j++) {
                    oa[i][j]   += pv0[i] * bvv[j];
                    oa[4+i][j] += pv1[i] * bvv[j];
                }
        }
    }
    #pragma unroll
    for (int i = 0; i < 8; i++) {
        int q = ((i & 4) ? 64 : 0) + ty * 4 + (i & 3);
        float inv = 1.f / l[i];
        float4 ov = make_float4(oa[i][0]*inv, oa[i][1]*inv,
                                oa[i][2]*inv, oa[i][3]*inv);
        int gi = (b * S_ + q0 + q) * C_ + n * HD_ + tx * 4;
        *(float4*)&g_f0[gi] = ov;
        uint32_t h0, l0v, h1, l1v;
        split2(ov.x, ov.y, h0, l0v);
        split2(ov.z, ov.w, h1, l1v);
        *(uint2*)&g_a0h[gi] = make_uint2(h0, h1);
        *(uint2*)&g_a0l[gi] = make_uint2(l0v, l1v);
    }
}

// ---------------------------------------------------------------------------
extern "C" void kernel_launch(void* const* d_in, const int* in_sizes, int n_in,
                              void* d_out, int out_size) {
    const float* x        = (const float*)d_in[0];
    const float* gn_scale = (const float*)d_in[1];
    const float* gn_bias  = (const float*)d_in[2];
    const float* qkv_w    = (const float*)d_in[3];
    const float* qkv_b    = (const float*)d_in[4];
    const float* proj_w   = (const float*)d_in[5];
    const float* proj_b   = (const float*)d_in[6];
    const float* inl_w    = (const float*)d_in[7];
    const float* inl_b    = (const float*)d_in[8];
    float* out = (float*)d_out;

    const int attn_smem = (8192 + 4096 + 64*68 + 8192) * 4;   // 99328 B
    cudaFuncSetAttribute(attn_kernel,
                         cudaFuncAttributeMaxDynamicSharedMemorySize, attn_smem);
    cudaFuncSetAttribute(qkv_kernel,
                         cudaFuncAttributeMaxDynamicSharedMemorySize, MMSM);
    cudaFuncSetAttribute(inl_kernel,
                         cudaFuncAttributeMaxDynamicSharedMemorySize, MMSM);
    cudaFuncSetAttribute(proj_kernel,
                         cudaFuncAttributeMaxDynamicSharedMemorySize, MMSM);

    convw_kernel<<<768, 256>>>(qkv_w,  0);
    convw_kernel<<<256, 256>>>(inl_w,  1);
    convw_kernel<<<256, 256>>>(proj_w, 2);
    gn_kernel   <<<64, 1024>>>(x, gn_scale, gn_bias);
    qkv_kernel  <<<dim3(64, 12), 256, MMSM>>>(qkv_b);
    attn_kernel <<<dim3(8, 64), 256, attn_smem>>>();
    inl_kernel  <<<dim3(4, 64), 256, MMSM>>>(0, inl_b);   // a0 -> a1
    inl_kernel  <<<dim3(4, 64), 256, MMSM>>>(1, inl_b);   // a1 -> a0
    inl_kernel  <<<dim3(4, 64), 256, MMSM>>>(0, inl_b);   // a0 -> a1
    proj_kernel <<<dim3(64, 4), 256, MMSM>>>(proj_b, x, out);
}